// round 5
// baseline (speedup 1.0000x reference)
#include <cuda_runtime.h>
#include <math.h>

// Problem constants
#define BB 2
#define EE 1024
#define SS 2048
#define HH 16
#define DD 64
#define BES (BB*EE*SS)          // 4,194,304 elements

// ---------------------------------------------------------------------------
// Scratch (device globals; no runtime allocation allowed)
// ---------------------------------------------------------------------------
__device__ float g_ql[BES], g_kl[BES], g_vl[BES];
__device__ float g_qr[BES], g_kr[BES], g_vr[BES];
__device__ float g_al[BES], g_ar[BES];
__device__ float g_lnout[BES];
__device__ float g_h1[2 * BES];
__device__ float g_wf[2 * EE * EE];     // fused W1@Wo
__device__ float g_lam;

// ---------------------------------------------------------------------------
// TF32 helpers
// ---------------------------------------------------------------------------
__device__ __forceinline__ unsigned f2tf32(float v) {
    unsigned r; asm("cvt.rna.tf32.f32 %0, %1;" : "=r"(r) : "f"(v)); return r;
}
__device__ __forceinline__ void mma_tf32(
    float& c0, float& c1, float& c2, float& c3,
    unsigned a0, unsigned a1, unsigned a2, unsigned a3,
    unsigned b0, unsigned b1)
{
    asm("mma.sync.aligned.m16n8k8.row.col.f32.tf32.tf32.f32 "
        "{%0,%1,%2,%3}, {%4,%5,%6,%7}, {%8,%9}, {%0,%1,%2,%3};"
        : "+f"(c0), "+f"(c1), "+f"(c2), "+f"(c3)
        : "r"(a0), "r"(a1), "r"(a2), "r"(a3), "r"(b0), "r"(b1));
}

// ---------------------------------------------------------------------------
// Tensor-core GEMM (3xTF32), double-buffered, 2 blocks/SM.
// C[b][m][n] = relu?(alpha*sum_k W[m][k]*X[b][k][n] + bias[m])
// Block tile 128x64, BK=16, 256 threads = 8 warps (2 warpM x 4 warpN),
// warp tile 64x16 = 4x2 m16n8k8 tiles. Fragments staged in SMEM in fragment
// order (conflict-free LDS, contiguous STS). Two 24KB buffers; next global
// tile prefetched into registers during the current MMAs. Small accumulator
// file (32 regs) keeps regs <=128 so two blocks co-reside per SM and cover
// each other's barrier/LDS latency.
//
// Per-buffer word layout: Ah[0..2047] Al[2048..4095] Bh[4096..5119] Bl[5120..6143]
// ---------------------------------------------------------------------------
#define GEMM_SMEM (2 * 6144 * 4)

__global__ __launch_bounds__(256, 2) void gemm_tc(
    const float* __restrict__ W, const float* __restrict__ X,
    float* __restrict__ C, int M, int K, int N,
    const float* __restrict__ bias, float alpha, int relu)
{
    extern __shared__ __align__(16) unsigned smp[];   // 2 x 6144 words

    const int t = threadIdx.x;
    const int lane = t & 31, wid = t >> 5;
    const int warpM = wid >> 2, warpN = wid & 3;
    const int bm = blockIdx.y << 7, bn = blockIdx.x << 6;
    const float* Xb = X + (size_t)blockIdx.z * K * N;
    float* Cb = C + (size_t)blockIdx.z * M * N;

    float acc[4][2][4];   // [mt][nt][creg]
#pragma unroll
    for (int a = 0; a < 4; ++a)
#pragma unroll
        for (int b = 0; b < 2; ++b)
#pragma unroll
            for (int c = 0; c < 4; ++c) acc[a][b][c] = 0.f;

    // Loader slot geometry (k0-independent).
    // A slot s (0..511): mtk=s>>5, ls=s&31 -> m_off=(mtk>>1)*16+(ls>>2),
    //   k_off=(mtk&1)*8+(ls&3); regs: +8 rows (reg&1), +4 cols (reg>>1)
    // B slot s (0..511): ntk=s>>5, ls=s&31 -> n_off=(ntk>>1)*8+(ls>>2),
    //   k_off=(ntk&1)*8+(ls&3); regs: +4 k for reg 1
    int amo[2], ako[2], bno[2], bko[2];
#pragma unroll
    for (int i = 0; i < 2; ++i) {
        int s = t + (i << 8), mtk = s >> 5, ls = s & 31;
        amo[i] = ((mtk >> 1) << 4) + (ls >> 2);
        ako[i] = ((mtk & 1) << 3) + (ls & 3);
        bno[i] = ((mtk >> 1) << 3) + (ls >> 2);
        bko[i] = ako[i];
    }

    float pa[2][4];   // prefetched A values
    float pb[2][2];   // prefetched B values

    auto loadG = [&](int k0) {
#pragma unroll
        for (int i = 0; i < 2; ++i) {
            const float* base = W + (size_t)(bm + amo[i]) * K + (k0 + ako[i]);
            pa[i][0] = base[0];
            pa[i][1] = base[(size_t)8 * K];
            pa[i][2] = base[4];
            pa[i][3] = base[(size_t)8 * K + 4];
        }
#pragma unroll
        for (int i = 0; i < 2; ++i) {
            const float* base = Xb + (size_t)(k0 + bko[i]) * N + bn + bno[i];
            pb[i][0] = base[0];
            pb[i][1] = base[(size_t)4 * N];
        }
    };

    auto storeS = [&](int buf) {
        unsigned* Ah = smp + buf * 6144;
        float*    Al = (float*)(smp + buf * 6144 + 2048);
        unsigned* Bh = smp + buf * 6144 + 4096;
        float*    Bl = (float*)(smp + buf * 6144 + 5120);
#pragma unroll
        for (int i = 0; i < 2; ++i) {
            int s = t + (i << 8);
            unsigned h0 = f2tf32(pa[i][0]), h1 = f2tf32(pa[i][1]);
            unsigned h2 = f2tf32(pa[i][2]), h3 = f2tf32(pa[i][3]);
            uint4 hv = {h0, h1, h2, h3};
            float4 lv = {pa[i][0] - __uint_as_float(h0), pa[i][1] - __uint_as_float(h1),
                         pa[i][2] - __uint_as_float(h2), pa[i][3] - __uint_as_float(h3)};
            *(uint4*)&Ah[s * 4] = hv;
            *(float4*)&Al[s * 4] = lv;
        }
#pragma unroll
        for (int i = 0; i < 2; ++i) {
            int s = t + (i << 8);
            unsigned h0 = f2tf32(pb[i][0]), h1 = f2tf32(pb[i][1]);
            uint2 hv = {h0, h1};
            float2 lv = {pb[i][0] - __uint_as_float(h0), pb[i][1] - __uint_as_float(h1)};
            *(uint2*)&Bh[s * 2] = hv;
            *(float2*)&Bl[s * 2] = lv;
        }
    };

    auto compute = [&](int buf) {
        const unsigned* Ah = smp + buf * 6144;
        const float*    Al = (const float*)(smp + buf * 6144 + 2048);
        const unsigned* Bh = smp + buf * 6144 + 4096;
        const float*    Bl = (const float*)(smp + buf * 6144 + 5120);
#pragma unroll
        for (int ks = 0; ks < 2; ++ks) {
            uint4 ah[4]; float4 al[4];
#pragma unroll
            for (int mt = 0; mt < 4; ++mt) {
                int idx = (((warpM * 4 + mt) * 2 + ks) * 32 + lane);
                ah[mt] = *(const uint4*)&Ah[idx * 4];
                al[mt] = *(const float4*)&Al[idx * 4];
            }
#pragma unroll
            for (int nt = 0; nt < 2; ++nt) {
                int idx = (((warpN * 2 + nt) * 2 + ks) * 32 + lane);
                uint2 bh = *(const uint2*)&Bh[idx * 2];
                float2 bl = *(const float2*)&Bl[idx * 2];
                unsigned bl0 = __float_as_uint(bl.x), bl1 = __float_as_uint(bl.y);
#pragma unroll
                for (int mt = 0; mt < 4; ++mt) {
                    float* c = acc[mt][nt];
                    mma_tf32(c[0], c[1], c[2], c[3],
                             ah[mt].x, ah[mt].y, ah[mt].z, ah[mt].w, bh.x, bh.y);
                    mma_tf32(c[0], c[1], c[2], c[3],
                             ah[mt].x, ah[mt].y, ah[mt].z, ah[mt].w, bl0, bl1);
                    mma_tf32(c[0], c[1], c[2], c[3],
                             __float_as_uint(al[mt].x), __float_as_uint(al[mt].y),
                             __float_as_uint(al[mt].z), __float_as_uint(al[mt].w),
                             bh.x, bh.y);
                }
            }
        }
    };

    // ---- pipelined main loop ----
    const int kiters = K >> 4;
    loadG(0);
    storeS(0);
    __syncthreads();
    for (int it = 0; it < kiters; ++it) {
        const int cur = it & 1;
        if (it + 1 < kiters) loadG((it + 1) << 4);   // LDGs fly during MMAs
        compute(cur);
        if (it + 1 < kiters) storeS(cur ^ 1);
        __syncthreads();
    }

    // ---- epilogue ----
    const int r = lane >> 2, j = lane & 3;
#pragma unroll
    for (int mt = 0; mt < 4; ++mt) {
        const int m0 = bm + warpM * 64 + mt * 16 + r;
        const float bv0 = bias ? bias[m0] : 0.f;
        const float bv1 = bias ? bias[m0 + 8] : 0.f;
#pragma unroll
        for (int nt = 0; nt < 2; ++nt) {
            const int n = bn + warpN * 16 + nt * 8 + j * 2;
            const float* c = acc[mt][nt];
            float r0 = alpha * c[0] + bv0, r1 = alpha * c[1] + bv0;
            float r2 = alpha * c[2] + bv1, r3 = alpha * c[3] + bv1;
            if (relu) {
                r0 = fmaxf(r0, 0.f); r1 = fmaxf(r1, 0.f);
                r2 = fmaxf(r2, 0.f); r3 = fmaxf(r3, 0.f);
            }
            float2 w0 = {r0, r1}, w1 = {r2, r3};
            *(float2*)&Cb[(size_t)m0 * N + n] = w0;
            *(float2*)&Cb[(size_t)(m0 + 8) * N + n] = w1;
        }
    }
}

// ---------------------------------------------------------------------------
// Flash attention (causal), fp32 scalar (known-good numerics).
// Both paths fused in one launch: z = path*BB + b.
// SMEM: Qs[64][128] | Ks[64][64] | Vt[64][68] | Ps[64][128]
// ---------------------------------------------------------------------------
#define ATTN_SMEM ((64*128 + 64*64 + 64*68 + 64*128) * 4)

__global__ __launch_bounds__(128) void attn_kernel(
    const float* __restrict__ Ql, const float* __restrict__ Kl,
    const float* __restrict__ Vl, float* __restrict__ Ol,
    const float* __restrict__ Qr, const float* __restrict__ Kr,
    const float* __restrict__ Vr, float* __restrict__ Or)
{
    extern __shared__ float sm[];
    float* Qs = sm;                  // [64][128]  Qs[d][q_local]
    float* Ks = sm + 64 * 128;       // [64][64]   Ks[d][t]
    float* Vt = Ks + 64 * 64;        // [64][68]   Vt[t][d] (pad 68)
    float* Ps = Vt + 64 * 68;        // [64][128]  Ps[t][q_local]

    const int tid = threadIdx.x;
    const int path = blockIdx.z >> 1;
    const int bz = blockIdx.z & 1;
    const float* Q = path ? Qr : Ql;
    const float* Kg = path ? Kr : Kl;
    const float* V = path ? Vr : Vl;
    float* O = path ? Or : Ol;

    const int qt = (gridDim.x - 1) - blockIdx.x;   // heavy tiles launch first
    const int q0 = qt << 7;
    const size_t base = ((size_t)bz * EE + (size_t)blockIdx.y * DD) * SS;
    const float* Qp = Q + base;
    const float* Kp = Kg + base;
    const float* Vp = V + base;
    const int q = q0 + tid;

    for (int f = tid; f < 64 * 32; f += 128) {
        int d = f >> 5, qc = (f & 31) << 2;
        *(float4*)&Qs[d * 128 + qc] =
            *(const float4*)&Qp[(size_t)d * SS + q0 + qc];
    }

    float o[64];
#pragma unroll
    for (int d = 0; d < 64; ++d) o[d] = 0.f;
    float mrow = -1e30f, lrow = 0.f;

    const int nt = qt * 2 + 2;
    for (int kt = 0; kt < nt; ++kt) {
        const int t0 = kt << 6;
        __syncthreads();
        for (int f = tid; f < 64 * 16; f += 128) {
            int d = f >> 4, tc = (f & 15) << 2;
            *(float4*)&Ks[d * 64 + tc] =
                *(const float4*)&Kp[(size_t)d * SS + t0 + tc];
        }
        for (int f = tid; f < 64 * 64; f += 128) {
            int d = f >> 6, tt = f & 63;
            Vt[tt * 68 + d] = Vp[(size_t)d * SS + t0 + tt];
        }
        __syncthreads();

        float s[64];
#pragma unroll
        for (int tt = 0; tt < 64; ++tt) s[tt] = 0.f;
#pragma unroll 4
        for (int d = 0; d < 64; ++d) {
            float qd = Qs[d * 128 + tid];
#pragma unroll
            for (int t4 = 0; t4 < 16; ++t4) {
                float4 k4 = *(const float4*)&Ks[d * 64 + (t4 << 2)];
                s[(t4 << 2) + 0] = fmaf(qd, k4.x, s[(t4 << 2) + 0]);
                s[(t4 << 2) + 1] = fmaf(qd, k4.y, s[(t4 << 2) + 1]);
                s[(t4 << 2) + 2] = fmaf(qd, k4.z, s[(t4 << 2) + 2]);
                s[(t4 << 2) + 3] = fmaf(qd, k4.w, s[(t4 << 2) + 3]);
            }
        }
#pragma unroll
        for (int tt = 0; tt < 64; ++tt)
            if (t0 + tt > q) s[tt] = -1e30f;

        float mx = mrow;
#pragma unroll
        for (int tt = 0; tt < 64; ++tt) mx = fmaxf(mx, s[tt]);
        float corr = __expf(mrow - mx);
        mrow = mx;
        lrow *= corr;
#pragma unroll
        for (int d = 0; d < 64; ++d) o[d] *= corr;
        float lsum = 0.f;
#pragma unroll
        for (int tt = 0; tt < 64; ++tt) {
            float p = __expf(s[tt] - mx);
            Ps[tt * 128 + tid] = p;
            lsum += p;
        }
        lrow += lsum;

        for (int tt = 0; tt < 64; ++tt) {
            float pt = Ps[tt * 128 + tid];
#pragma unroll
            for (int d4 = 0; d4 < 16; ++d4) {
                float4 v4 = *(const float4*)&Vt[tt * 68 + (d4 << 2)];
                o[(d4 << 2) + 0] = fmaf(pt, v4.x, o[(d4 << 2) + 0]);
                o[(d4 << 2) + 1] = fmaf(pt, v4.y, o[(d4 << 2) + 1]);
                o[(d4 << 2) + 2] = fmaf(pt, v4.z, o[(d4 << 2) + 2]);
                o[(d4 << 2) + 3] = fmaf(pt, v4.w, o[(d4 << 2) + 3]);
            }
        }
    }

    const float inv = 1.f / lrow;
    float* Op = O + base;
#pragma unroll
    for (int d = 0; d < 64; ++d)
        Op[(size_t)d * SS + q] = o[d] * inv;
}

// ---------------------------------------------------------------------------
// lambda = exp(sum lam_q_l*lam_k_l) - exp(sum lam_q_r*lam_k_r) + 0.1
// ---------------------------------------------------------------------------
__global__ void lam_kernel(const float* __restrict__ ql, const float* __restrict__ kl,
                           const float* __restrict__ qr, const float* __restrict__ kr)
{
    const int t = threadIdx.x;   // 32 threads
    float a = ql[t] * kl[t] + ql[t + 32] * kl[t + 32];
    float b = qr[t] * kr[t] + qr[t + 32] * kr[t + 32];
#pragma unroll
    for (int off = 16; off > 0; off >>= 1) {
        a += __shfl_xor_sync(0xffffffffu, a, off);
        b += __shfl_xor_sync(0xffffffffu, b, off);
    }
    if (t == 0) g_lam = expf(a) - expf(b) + 0.1f;
}

// ---------------------------------------------------------------------------
// combined = attn_l - lam*attn_r; LayerNorm over E (biased var, eps 1e-5).
// ---------------------------------------------------------------------------
__global__ __launch_bounds__(512) void ln_kernel(
    const float* __restrict__ al, const float* __restrict__ ar,
    const float* __restrict__ gg, const float* __restrict__ bbv,
    float* __restrict__ out)
{
    __shared__ float ps[16][32], pq[16][32], smu[32], srs[32];
    const int tid = threadIdx.x;
    const int ty = tid >> 5, sl = tid & 31;
    const int b = blockIdx.x >> 6;
    const int s = ((blockIdx.x & 63) << 5) + sl;
    const float lam = g_lam;
    const size_t col = (size_t)b * EE * SS + s;
    const int e0 = ty << 6;

    float sum = 0.f, sq = 0.f;
    for (int e = e0; e < e0 + 64; ++e) {
        size_t idx = col + (size_t)e * SS;
        float c = al[idx] - lam * ar[idx];
        sum += c; sq += c * c;
    }
    ps[ty][sl] = sum; pq[ty][sl] = sq;
    __syncthreads();
    if (ty == 0) {
        float ts = 0.f, tq = 0.f;
#pragma unroll
        for (int r = 0; r < 16; ++r) { ts += ps[r][sl]; tq += pq[r][sl]; }
        float mu = ts * (1.f / EE);
        float var = tq * (1.f / EE) - mu * mu;
        smu[sl] = mu;
        srs[sl] = rsqrtf(var + 1e-5f);
    }
    __syncthreads();
    const float mu = smu[sl], rs = srs[sl];
    for (int e = e0; e < e0 + 64; ++e) {
        size_t idx = col + (size_t)e * SS;
        float c = al[idx] - lam * ar[idx];
        out[idx] = (c - mu) * rs * gg[e] + bbv[e];
    }
}

// ---------------------------------------------------------------------------
// Launch
// ---------------------------------------------------------------------------
static float* sym_addr(const void* symbol)
{
    void* p = nullptr;
    cudaGetSymbolAddress(&p, symbol);
    return (float*)p;
}

extern "C" void kernel_launch(void* const* d_in, const int* in_sizes, int n_in,
                              void* d_out, int out_size)
{
    const float* left  = (const float*)d_in[0];
    const float* right = (const float*)d_in[1];
    const float* Wq_l  = (const float*)d_in[2];
    const float* Wk_l  = (const float*)d_in[3];
    const float* Wv_l  = (const float*)d_in[4];
    const float* Wq_r  = (const float*)d_in[5];
    const float* Wk_r  = (const float*)d_in[6];
    const float* Wv_r  = (const float*)d_in[7];
    const float* Wo    = (const float*)d_in[8];
    const float* lql   = (const float*)d_in[9];
    const float* lkl   = (const float*)d_in[10];
    const float* lqr   = (const float*)d_in[11];
    const float* lkr   = (const float*)d_in[12];
    const float* ln_g  = (const float*)d_in[13];
    const float* ln_b  = (const float*)d_in[14];
    const float* W1    = (const float*)d_in[15];
    const float* b1    = (const float*)d_in[16];
    const float* W2    = (const float*)d_in[17];
    const float* b2    = (const float*)d_in[18];
    float* out = (float*)d_out;

    float* ql = sym_addr(g_ql); float* kl = sym_addr(g_kl); float* vl = sym_addr(g_vl);
    float* qr = sym_addr(g_qr); float* kr = sym_addr(g_kr); float* vr = sym_addr(g_vr);
    float* al = sym_addr(g_al); float* ar = sym_addr(g_ar);
    float* lno = sym_addr(g_lnout);
    float* h1 = sym_addr(g_h1);
    float* wf = sym_addr(g_wf);

    const float qscale = 0.125f;   // D^-0.5 folded into q projection

    cudaFuncSetAttribute(gemm_tc, cudaFuncAttributeMaxDynamicSharedMemorySize,
                         GEMM_SMEM);
    cudaFuncSetAttribute(attn_kernel, cudaFuncAttributeMaxDynamicSharedMemorySize,
                         ATTN_SMEM);

    dim3 blk(256);
    dim3 gp(SS / 64, EE / 128, BB);          // (32, 8, 2)
    dim3 gp1(SS / 64, (2 * EE) / 128, BB);   // (32, 16, 2)
    dim3 gpw(EE / 64, (2 * EE) / 128, 1);    // Wf = W1 @ Wo precompute

    // Wf precompute early (independent of activations)
    gemm_tc<<<gpw, blk, GEMM_SMEM>>>(W1, Wo, wf, 2 * EE, EE, EE, nullptr, 1.f, 0);

    // QKV projections (tensor-core 3xTF32, native [B,E,S] layout)
    gemm_tc<<<gp, blk, GEMM_SMEM>>>(Wq_l, left,  ql, EE, EE, SS, nullptr, qscale, 0);
    gemm_tc<<<gp, blk, GEMM_SMEM>>>(Wk_l, left,  kl, EE, EE, SS, nullptr, 1.f, 0);
    gemm_tc<<<gp, blk, GEMM_SMEM>>>(Wv_l, left,  vl, EE, EE, SS, nullptr, 1.f, 0);
    gemm_tc<<<gp, blk, GEMM_SMEM>>>(Wq_r, right, qr, EE, EE, SS, nullptr, qscale, 0);
    gemm_tc<<<gp, blk, GEMM_SMEM>>>(Wk_r, right, kr, EE, EE, SS, nullptr, 1.f, 0);
    gemm_tc<<<gp, blk, GEMM_SMEM>>>(Wv_r, right, vr, EE, EE, SS, nullptr, 1.f, 0);

    // attention: both paths in one launch (z = path*2 + b)
    dim3 ga(SS / 128, HH, 2 * BB);           // (16, 16, 4)
    attn_kernel<<<ga, 128, ATTN_SMEM>>>(ql, kl, vl, al, qr, kr, vr, ar);

    // lambda, combine + LN
    lam_kernel<<<1, 32>>>(lql, lkl, lqr, lkr);
    ln_kernel<<<BB * (SS / 32), 512>>>(al, ar, ln_g, ln_b, lno);

    // fused (W1@Wo) + relu, then W2 straight into d_out ([B,E,S])
    gemm_tc<<<gp1, blk, GEMM_SMEM>>>(wf, lno, h1,  2 * EE, EE,     SS, b1, 1.f, 1);
    gemm_tc<<<gp,  blk, GEMM_SMEM>>>(W2, h1,  out, EE,     2 * EE, SS, b2, 1.f, 0);
}

// round 6
// speedup vs baseline: 1.5259x; 1.5259x over previous
#include <cuda_runtime.h>
#include <cuda_bf16.h>
#include <math.h>

// Problem constants
#define BB 2
#define EE 1024
#define SS 2048
#define HH 16
#define DD 64
#define BES (BB*EE*SS)          // 4,194,304 elements

// ---------------------------------------------------------------------------
// Scratch (device globals; no runtime allocation allowed)
// ---------------------------------------------------------------------------
__device__ float g_ql[BES], g_kl[BES], g_vl[BES];
__device__ float g_qr[BES], g_kr[BES], g_vr[BES];
__device__ float g_al[BES], g_ar[BES];
__device__ float g_lnout[BES];
__device__ float g_h1[2 * BES];
__device__ float g_wf[2 * EE * EE];     // fused W1@Wo
__device__ float g_lam;

// ---------------------------------------------------------------------------
// bf16 split helpers
// ---------------------------------------------------------------------------
__device__ __forceinline__ unsigned bf2pack(float x, float y) {
    __nv_bfloat162 h = __floats2bfloat162_rn(x, y);
    return *reinterpret_cast<unsigned*>(&h);
}
__device__ __forceinline__ float bfhi(float x) {
    return __bfloat162float(__float2bfloat16(x));
}
__device__ __forceinline__ void mma_bf16(
    float& c0, float& c1, float& c2, float& c3,
    unsigned a0, unsigned a1, unsigned a2, unsigned a3,
    unsigned b0, unsigned b1)
{
    asm("mma.sync.aligned.m16n8k16.row.col.f32.bf16.bf16.f32 "
        "{%0,%1,%2,%3}, {%4,%5,%6,%7}, {%8,%9}, {%0,%1,%2,%3};"
        : "+f"(c0), "+f"(c1), "+f"(c2), "+f"(c3)
        : "r"(a0), "r"(a1), "r"(a2), "r"(a3), "r"(b0), "r"(b1));
}

// ---------------------------------------------------------------------------
// Tensor-core GEMM body (3-product split-bf16 m16n8k16), double-buffered.
// C[m][n] = relu?(alpha * sum_k W[m][k] * Xb[k][n] + bias[m])
// Block tile 128x128, BK=16, 256 threads = 8 warps (2 warpM x 4 warpN),
// warp tile 64x32 = 4x4 m16n8k16 tiles. hi/lo bf16 fragments staged in SMEM
// in fragment order (conflict-free LDS.128/LDS.64, contiguous STS).
//
// m16n8k16 bf16 fragment layouts (PTX ISA), g=lane>>2, c=lane&3:
//   A: a0=(g, 2c|2c+1) a1=(g+8, same) a2=(g, 2c+8|2c+9) a3=(g+8, same)
//   B: b0=(k=2c|2c+1, n=g) b1=(k=2c+8|2c+9, n=g)
//   C: c0,c1=(g, 2c,2c+1) c2,c3=(g+8, ...)
//
// Per-buffer word layout: Ah[0..1023] Al[1024..2047] Bh[2048..3071] Bl[3072..4095]
// ---------------------------------------------------------------------------
#define GEMM_SMEM (2 * 4096 * 4)

__device__ __forceinline__ void gemm_body(
    const float* __restrict__ W, const float* __restrict__ Xb,
    float* __restrict__ Cb, int M, int K, int N,
    const float* __restrict__ bias, float alpha, int relu,
    unsigned* smp)
{
    const int t = threadIdx.x;
    const int lane = t & 31, wid = t >> 5;
    const int warpM = wid >> 2, warpN = wid & 3;
    const int bm = blockIdx.y << 7, bn = blockIdx.x << 7;

    float acc[4][4][4];   // [mt][nt][creg]
#pragma unroll
    for (int a = 0; a < 4; ++a)
#pragma unroll
        for (int b = 0; b < 4; ++b)
#pragma unroll
            for (int c = 0; c < 4; ++c) acc[a][b][c] = 0.f;

    // A loader: slot = t (256 slots, 8 mt-tiles x 32 lanes), 4 regs x float2
    const int amt = t >> 5, als = t & 31;
    const int amo = (amt << 4) + (als >> 2);       // m offset in tile
    const int ako = (als & 3) << 1;                // k offset (pair base)
    // B loader: slots s = t, t+256 (512 slots, 16 nt-tiles x 32 lanes), 2 regs
    int bno[2], bko[2];
#pragma unroll
    for (int i = 0; i < 2; ++i) {
        int s = t + (i << 8), nt = s >> 5, ls = s & 31;
        bno[i] = (nt << 3) + (ls >> 2);
        bko[i] = (ls & 3) << 1;
    }

    float2 pa[4];      // A prefetch: 4 regs x (k, k+1)
    float2 pb[2][2];   // B prefetch: 2 slots x 2 regs x (k, k+1)

    auto loadG = [&](int k0) {
        const float* ap = W + (size_t)(bm + amo) * K + (k0 + ako);
        pa[0] = *(const float2*)ap;
        pa[1] = *(const float2*)(ap + (size_t)8 * K);
        pa[2] = *(const float2*)(ap + 8);
        pa[3] = *(const float2*)(ap + (size_t)8 * K + 8);
#pragma unroll
        for (int i = 0; i < 2; ++i) {
            const float* bp = Xb + (size_t)(k0 + bko[i]) * N + bn + bno[i];
            pb[i][0] = make_float2(bp[0], bp[N]);
            pb[i][1] = make_float2(bp[(size_t)8 * N], bp[(size_t)9 * N]);
        }
    };

    auto storeS = [&](int buf) {
        unsigned* Ah = smp + buf * 4096;
        unsigned* Al = smp + buf * 4096 + 1024;
        unsigned* Bh = smp + buf * 4096 + 2048;
        unsigned* Bl = smp + buf * 4096 + 3072;
        uint4 hv, lv;
        {
            float hx, hy;
            unsigned h[4], l[4];
#pragma unroll
            for (int r = 0; r < 4; ++r) {
                hx = bfhi(pa[r].x); hy = bfhi(pa[r].y);
                h[r] = bf2pack(pa[r].x, pa[r].y);
                l[r] = bf2pack(pa[r].x - hx, pa[r].y - hy);
            }
            hv = make_uint4(h[0], h[1], h[2], h[3]);
            lv = make_uint4(l[0], l[1], l[2], l[3]);
            *(uint4*)&Ah[t * 4] = hv;
            *(uint4*)&Al[t * 4] = lv;
        }
#pragma unroll
        for (int i = 0; i < 2; ++i) {
            int s = t + (i << 8);
            unsigned h0, h1, l0, l1;
            float hx, hy;
            hx = bfhi(pb[i][0].x); hy = bfhi(pb[i][0].y);
            h0 = bf2pack(pb[i][0].x, pb[i][0].y);
            l0 = bf2pack(pb[i][0].x - hx, pb[i][0].y - hy);
            hx = bfhi(pb[i][1].x); hy = bfhi(pb[i][1].y);
            h1 = bf2pack(pb[i][1].x, pb[i][1].y);
            l1 = bf2pack(pb[i][1].x - hx, pb[i][1].y - hy);
            *(uint2*)&Bh[s * 2] = make_uint2(h0, h1);
            *(uint2*)&Bl[s * 2] = make_uint2(l0, l1);
        }
    };

    auto compute = [&](int buf) {
        const unsigned* Ah = smp + buf * 4096;
        const unsigned* Al = smp + buf * 4096 + 1024;
        const unsigned* Bh = smp + buf * 4096 + 2048;
        const unsigned* Bl = smp + buf * 4096 + 3072;
        uint4 ah[4], alr[4];
#pragma unroll
        for (int mt = 0; mt < 4; ++mt) {
            int idx = (warpM * 4 + mt) * 32 + lane;
            ah[mt]  = *(const uint4*)&Ah[idx * 4];
            alr[mt] = *(const uint4*)&Al[idx * 4];
        }
#pragma unroll
        for (int nt = 0; nt < 4; ++nt) {
            int idx = (warpN * 4 + nt) * 32 + lane;
            uint2 bh = *(const uint2*)&Bh[idx * 2];
            uint2 bl = *(const uint2*)&Bl[idx * 2];
#pragma unroll
            for (int mt = 0; mt < 4; ++mt) {
                float* c = acc[mt][nt];
                mma_bf16(c[0], c[1], c[2], c[3],
                         ah[mt].x, ah[mt].y, ah[mt].z, ah[mt].w, bh.x, bh.y);
                mma_bf16(c[0], c[1], c[2], c[3],
                         ah[mt].x, ah[mt].y, ah[mt].z, ah[mt].w, bl.x, bl.y);
                mma_bf16(c[0], c[1], c[2], c[3],
                         alr[mt].x, alr[mt].y, alr[mt].z, alr[mt].w, bh.x, bh.y);
            }
        }
    };

    // ---- pipelined main loop ----
    const int kiters = K >> 4;
    loadG(0);
    storeS(0);
    __syncthreads();
    for (int it = 0; it < kiters; ++it) {
        const int cur = it & 1;
        if (it + 1 < kiters) loadG((it + 1) << 4);   // LDGs fly during MMAs
        compute(cur);
        if (it + 1 < kiters) storeS(cur ^ 1);
        __syncthreads();
    }

    // ---- epilogue ----
    const int r = lane >> 2, j = lane & 3;
#pragma unroll
    for (int mt = 0; mt < 4; ++mt) {
        const int m0 = bm + warpM * 64 + mt * 16 + r;
        const float bv0 = bias ? bias[m0] : 0.f;
        const float bv1 = bias ? bias[m0 + 8] : 0.f;
#pragma unroll
        for (int nt = 0; nt < 4; ++nt) {
            const int n = bn + warpN * 32 + nt * 8 + j * 2;
            const float* c = acc[mt][nt];
            float r0 = alpha * c[0] + bv0, r1 = alpha * c[1] + bv0;
            float r2 = alpha * c[2] + bv1, r3 = alpha * c[3] + bv1;
            if (relu) {
                r0 = fmaxf(r0, 0.f); r1 = fmaxf(r1, 0.f);
                r2 = fmaxf(r2, 0.f); r3 = fmaxf(r3, 0.f);
            }
            float2 w0 = {r0, r1}, w1 = {r2, r3};
            *(float2*)&Cb[(size_t)m0 * N + n] = w0;
            *(float2*)&Cb[(size_t)(m0 + 8) * N + n] = w1;
        }
    }
}

// Generic GEMM launchable (z = batch)
__global__ __launch_bounds__(256) void gemm_tc(
    const float* __restrict__ W, const float* __restrict__ X,
    float* __restrict__ C, int M, int K, int N,
    const float* __restrict__ bias, float alpha, int relu)
{
    extern __shared__ __align__(16) unsigned smp[];
    gemm_body(W, X + (size_t)blockIdx.z * K * N, C + (size_t)blockIdx.z * M * N,
              M, K, N, bias, alpha, relu, smp);
}

// All 6 QKV projections in one launch: z = which*2 + batch, which in 0..5
__global__ __launch_bounds__(256) void gemm_qkv(
    const float* __restrict__ Wq_l, const float* __restrict__ Wk_l,
    const float* __restrict__ Wv_l, const float* __restrict__ Wq_r,
    const float* __restrict__ Wk_r, const float* __restrict__ Wv_r,
    const float* __restrict__ left, const float* __restrict__ right,
    float* ql, float* kl, float* vl, float* qr, float* kr, float* vr,
    float qscale)
{
    extern __shared__ __align__(16) unsigned smp[];
    const int z = blockIdx.z, which = z >> 1, b = z & 1;
    const float* Ws[6] = {Wq_l, Wk_l, Wv_l, Wq_r, Wk_r, Wv_r};
    float*       Cs[6] = {ql, kl, vl, qr, kr, vr};
    const float* X = (which < 3) ? left : right;
    const float alpha = (which == 0 || which == 3) ? qscale : 1.f;
    gemm_body(Ws[which], X + (size_t)b * EE * SS, Cs[which] + (size_t)b * EE * SS,
              EE, EE, SS, nullptr, alpha, 0, smp);
}

// ---------------------------------------------------------------------------
// Flash attention (causal), fp32 scalar (known-good numerics).
// Both paths fused in one launch: z = path*BB + b.
// SMEM: Qs[64][128] | Ks[64][64] | Vt[64][68] | Ps[64][128]
// ---------------------------------------------------------------------------
#define ATTN_SMEM ((64*128 + 64*64 + 64*68 + 64*128) * 4)

__global__ __launch_bounds__(128) void attn_kernel(
    const float* __restrict__ Ql, const float* __restrict__ Kl,
    const float* __restrict__ Vl, float* __restrict__ Ol,
    const float* __restrict__ Qr, const float* __restrict__ Kr,
    const float* __restrict__ Vr, float* __restrict__ Or)
{
    extern __shared__ float sm[];
    float* Qs = sm;                  // [64][128]  Qs[d][q_local]
    float* Ks = sm + 64 * 128;       // [64][64]   Ks[d][t]
    float* Vt = Ks + 64 * 64;        // [64][68]   Vt[t][d] (pad 68)
    float* Ps = Vt + 64 * 68;        // [64][128]  Ps[t][q_local]

    const int tid = threadIdx.x;
    const int path = blockIdx.z >> 1;
    const int bz = blockIdx.z & 1;
    const float* Q = path ? Qr : Ql;
    const float* Kg = path ? Kr : Kl;
    const float* V = path ? Vr : Vl;
    float* O = path ? Or : Ol;

    const int qt = (gridDim.x - 1) - blockIdx.x;   // heavy tiles launch first
    const int q0 = qt << 7;
    const size_t base = ((size_t)bz * EE + (size_t)blockIdx.y * DD) * SS;
    const float* Qp = Q + base;
    const float* Kp = Kg + base;
    const float* Vp = V + base;
    const int q = q0 + tid;

    for (int f = tid; f < 64 * 32; f += 128) {
        int d = f >> 5, qc = (f & 31) << 2;
        *(float4*)&Qs[d * 128 + qc] =
            *(const float4*)&Qp[(size_t)d * SS + q0 + qc];
    }

    float o[64];
#pragma unroll
    for (int d = 0; d < 64; ++d) o[d] = 0.f;
    float mrow = -1e30f, lrow = 0.f;

    const int nt = qt * 2 + 2;
    for (int kt = 0; kt < nt; ++kt) {
        const int t0 = kt << 6;
        __syncthreads();
        for (int f = tid; f < 64 * 16; f += 128) {
            int d = f >> 4, tc = (f & 15) << 2;
            *(float4*)&Ks[d * 64 + tc] =
                *(const float4*)&Kp[(size_t)d * SS + t0 + tc];
        }
        for (int f = tid; f < 64 * 64; f += 128) {
            int d = f >> 6, tt = f & 63;
            Vt[tt * 68 + d] = Vp[(size_t)d * SS + t0 + tt];
        }
        __syncthreads();

        float s[64];
#pragma unroll
        for (int tt = 0; tt < 64; ++tt) s[tt] = 0.f;
#pragma unroll 4
        for (int d = 0; d < 64; ++d) {
            float qd = Qs[d * 128 + tid];
#pragma unroll
            for (int t4 = 0; t4 < 16; ++t4) {
                float4 k4 = *(const float4*)&Ks[d * 64 + (t4 << 2)];
                s[(t4 << 2) + 0] = fmaf(qd, k4.x, s[(t4 << 2) + 0]);
                s[(t4 << 2) + 1] = fmaf(qd, k4.y, s[(t4 << 2) + 1]);
                s[(t4 << 2) + 2] = fmaf(qd, k4.z, s[(t4 << 2) + 2]);
                s[(t4 << 2) + 3] = fmaf(qd, k4.w, s[(t4 << 2) + 3]);
            }
        }
#pragma unroll
        for (int tt = 0; tt < 64; ++tt)
            if (t0 + tt > q) s[tt] = -1e30f;

        float mx = mrow;
#pragma unroll
        for (int tt = 0; tt < 64; ++tt) mx = fmaxf(mx, s[tt]);
        float corr = __expf(mrow - mx);
        mrow = mx;
        lrow *= corr;
#pragma unroll
        for (int d = 0; d < 64; ++d) o[d] *= corr;
        float lsum = 0.f;
#pragma unroll
        for (int tt = 0; tt < 64; ++tt) {
            float p = __expf(s[tt] - mx);
            Ps[tt * 128 + tid] = p;
            lsum += p;
        }
        lrow += lsum;

        for (int tt = 0; tt < 64; ++tt) {
            float pt = Ps[tt * 128 + tid];
#pragma unroll
            for (int d4 = 0; d4 < 16; ++d4) {
                float4 v4 = *(const float4*)&Vt[tt * 68 + (d4 << 2)];
                o[(d4 << 2) + 0] = fmaf(pt, v4.x, o[(d4 << 2) + 0]);
                o[(d4 << 2) + 1] = fmaf(pt, v4.y, o[(d4 << 2) + 1]);
                o[(d4 << 2) + 2] = fmaf(pt, v4.z, o[(d4 << 2) + 2]);
                o[(d4 << 2) + 3] = fmaf(pt, v4.w, o[(d4 << 2) + 3]);
            }
        }
    }

    const float inv = 1.f / lrow;
    float* Op = O + base;
#pragma unroll
    for (int d = 0; d < 64; ++d)
        Op[(size_t)d * SS + q] = o[d] * inv;
}

// ---------------------------------------------------------------------------
// lambda = exp(sum lam_q_l*lam_k_l) - exp(sum lam_q_r*lam_k_r) + 0.1
// ---------------------------------------------------------------------------
__global__ void lam_kernel(const float* __restrict__ ql, const float* __restrict__ kl,
                           const float* __restrict__ qr, const float* __restrict__ kr)
{
    const int t = threadIdx.x;   // 32 threads
    float a = ql[t] * kl[t] + ql[t + 32] * kl[t + 32];
    float b = qr[t] * kr[t] + qr[t + 32] * kr[t + 32];
#pragma unroll
    for (int off = 16; off > 0; off >>= 1) {
        a += __shfl_xor_sync(0xffffffffu, a, off);
        b += __shfl_xor_sync(0xffffffffu, b, off);
    }
    if (t == 0) g_lam = expf(a) - expf(b) + 0.1f;
}

// ---------------------------------------------------------------------------
// combined = attn_l - lam*attn_r; LayerNorm over E (biased var, eps 1e-5).
// ---------------------------------------------------------------------------
__global__ __launch_bounds__(512) void ln_kernel(
    const float* __restrict__ al, const float* __restrict__ ar,
    const float* __restrict__ gg, const float* __restrict__ bbv,
    float* __restrict__ out)
{
    __shared__ float ps[16][32], pq[16][32], smu[32], srs[32];
    const int tid = threadIdx.x;
    const int ty = tid >> 5, sl = tid & 31;
    const int b = blockIdx.x >> 6;
    const int s = ((blockIdx.x & 63) << 5) + sl;
    const float lam = g_lam;
    const size_t col = (size_t)b * EE * SS + s;
    const int e0 = ty << 6;

    float sum = 0.f, sq = 0.f;
    for (int e = e0; e < e0 + 64; ++e) {
        size_t idx = col + (size_t)e * SS;
        float c = al[idx] - lam * ar[idx];
        sum += c; sq += c * c;
    }
    ps[ty][sl] = sum; pq[ty][sl] = sq;
    __syncthreads();
    if (ty == 0) {
        float ts = 0.f, tq = 0.f;
#pragma unroll
        for (int r = 0; r < 16; ++r) { ts += ps[r][sl]; tq += pq[r][sl]; }
        float mu = ts * (1.f / EE);
        float var = tq * (1.f / EE) - mu * mu;
        smu[sl] = mu;
        srs[sl] = rsqrtf(var + 1e-5f);
    }
    __syncthreads();
    const float mu = smu[sl], rs = srs[sl];
    for (int e = e0; e < e0 + 64; ++e) {
        size_t idx = col + (size_t)e * SS;
        float c = al[idx] - lam * ar[idx];
        out[idx] = (c - mu) * rs * gg[e] + bbv[e];
    }
}

// ---------------------------------------------------------------------------
// Launch
// ---------------------------------------------------------------------------
static float* sym_addr(const void* symbol)
{
    void* p = nullptr;
    cudaGetSymbolAddress(&p, symbol);
    return (float*)p;
}

extern "C" void kernel_launch(void* const* d_in, const int* in_sizes, int n_in,
                              void* d_out, int out_size)
{
    const float* left  = (const float*)d_in[0];
    const float* right = (const float*)d_in[1];
    const float* Wq_l  = (const float*)d_in[2];
    const float* Wk_l  = (const float*)d_in[3];
    const float* Wv_l  = (const float*)d_in[4];
    const float* Wq_r  = (const float*)d_in[5];
    const float* Wk_r  = (const float*)d_in[6];
    const float* Wv_r  = (const float*)d_in[7];
    const float* Wo    = (const float*)d_in[8];
    const float* lql   = (const float*)d_in[9];
    const float* lkl   = (const float*)d_in[10];
    const float* lqr   = (const float*)d_in[11];
    const float* lkr   = (const float*)d_in[12];
    const float* ln_g  = (const float*)d_in[13];
    const float* ln_b  = (const float*)d_in[14];
    const float* W1    = (const float*)d_in[15];
    const float* b1    = (const float*)d_in[16];
    const float* W2    = (const float*)d_in[17];
    const float* b2    = (const float*)d_in[18];
    float* out = (float*)d_out;

    float* ql = sym_addr(g_ql); float* kl = sym_addr(g_kl); float* vl = sym_addr(g_vl);
    float* qr = sym_addr(g_qr); float* kr = sym_addr(g_kr); float* vr = sym_addr(g_vr);
    float* al = sym_addr(g_al); float* ar = sym_addr(g_ar);
    float* lno = sym_addr(g_lnout);
    float* h1 = sym_addr(g_h1);
    float* wf = sym_addr(g_wf);

    const float qscale = 0.125f;   // D^-0.5 folded into q projection

    cudaFuncSetAttribute(gemm_tc, cudaFuncAttributeMaxDynamicSharedMemorySize,
                         GEMM_SMEM);
    cudaFuncSetAttribute(gemm_qkv, cudaFuncAttributeMaxDynamicSharedMemorySize,
                         GEMM_SMEM);
    cudaFuncSetAttribute(attn_kernel, cudaFuncAttributeMaxDynamicSharedMemorySize,
                         ATTN_SMEM);

    dim3 blk(256);
    dim3 gp(SS / 128, EE / 128, BB);         // (16, 8, 2)
    dim3 gp1(SS / 128, (2 * EE) / 128, BB);  // (16, 16, 2)
    dim3 gpw(EE / 128, (2 * EE) / 128, 1);   // Wf = W1 @ Wo precompute
    dim3 gq(SS / 128, EE / 128, 6 * BB);     // all 6 QKV GEMMs, z = which*2+b

    // Wf precompute early (independent of activations)
    gemm_tc<<<gpw, blk, GEMM_SMEM>>>(W1, Wo, wf, 2 * EE, EE, EE, nullptr, 1.f, 0);

    // QKV projections: one launch, 1536 blocks (amortizes wave tails)
    gemm_qkv<<<gq, blk, GEMM_SMEM>>>(Wq_l, Wk_l, Wv_l, Wq_r, Wk_r, Wv_r,
                                     left, right, ql, kl, vl, qr, kr, vr, qscale);

    // attention: both paths in one launch (z = path*2 + b)
    dim3 ga(SS / 128, HH, 2 * BB);           // (16, 16, 4)
    attn_kernel<<<ga, 128, ATTN_SMEM>>>(ql, kl, vl, al, qr, kr, vr, ar);

    // lambda, combine + LN
    lam_kernel<<<1, 32>>>(lql, lkl, lqr, lkr);
    ln_kernel<<<BB * (SS / 32), 512>>>(al, ar, ln_g, ln_b, lno);

    // fused (W1@Wo) + relu, then W2 straight into d_out ([B,E,S])
    gemm_tc<<<gp1, blk, GEMM_SMEM>>>(wf, lno, h1,  2 * EE, EE,     SS, b1, 1.f, 1);
    gemm_tc<<<gp,  blk, GEMM_SMEM>>>(W2, h1,  out, EE,     2 * EE, SS, b2, 1.f, 0);
}

// round 7
// speedup vs baseline: 2.7266x; 1.7869x over previous
#include <cuda_runtime.h>
#include <cuda_bf16.h>
#include <math.h>

// Problem constants
#define BB 2
#define EE 1024
#define SS 2048
#define HH 16
#define DD 64
#define BES (BB*EE*SS)          // 4,194,304 elements

// ---------------------------------------------------------------------------
// Scratch (device globals; no runtime allocation allowed)
// ---------------------------------------------------------------------------
__device__ float g_ql[BES], g_kl[BES], g_vl[BES];
__device__ float g_qr[BES], g_kr[BES], g_vr[BES];
__device__ float g_al[BES], g_ar[BES];
__device__ float g_lnout[BES];
__device__ float g_h1[2 * BES];
__device__ float g_wf[2 * EE * EE];     // fused W1@Wo
__device__ float g_lam;

// ---------------------------------------------------------------------------
// bf16 split helpers
// ---------------------------------------------------------------------------
__device__ __forceinline__ unsigned bf2pack(float x, float y) {
    __nv_bfloat162 h = __floats2bfloat162_rn(x, y);
    return *reinterpret_cast<unsigned*>(&h);
}
__device__ __forceinline__ float bfhi(float x) {
    return __bfloat162float(__float2bfloat16(x));
}
__device__ __forceinline__ void mma_bf16(
    float& c0, float& c1, float& c2, float& c3,
    unsigned a0, unsigned a1, unsigned a2, unsigned a3,
    unsigned b0, unsigned b1)
{
    asm("mma.sync.aligned.m16n8k16.row.col.f32.bf16.bf16.f32 "
        "{%0,%1,%2,%3}, {%4,%5,%6,%7}, {%8,%9}, {%0,%1,%2,%3};"
        : "+f"(c0), "+f"(c1), "+f"(c2), "+f"(c3)
        : "r"(a0), "r"(a1), "r"(a2), "r"(a3), "r"(b0), "r"(b1));
}

// exp2 via FMA-pipe polynomial (degree-5 Taylor on f in [-0.5,0.5], rel ~2e-6).
// Avoids the MUFU throughput ceiling (134M exps in attention).
__device__ __forceinline__ float exp2p(float z) {
    z = fmaxf(z, -100.f);
    float n = rintf(z);
    float f = z - n;
    float p = 0.00133335581f;
    p = fmaf(p, f, 0.00961812911f);
    p = fmaf(p, f, 0.05550410866f);
    p = fmaf(p, f, 0.24022650696f);
    p = fmaf(p, f, 0.69314718056f);
    p = fmaf(p, f, 1.0f);
    float sc = __int_as_float(((int)n + 127) << 23);
    return p * sc;
}

// ---------------------------------------------------------------------------
// Tensor-core GEMM body (3-product split-bf16 m16n8k16), double-buffered.
// (unchanged from the passing round-6 build)
// ---------------------------------------------------------------------------
#define GEMM_SMEM (2 * 4096 * 4)

__device__ __forceinline__ void gemm_body(
    const float* __restrict__ W, const float* __restrict__ Xb,
    float* __restrict__ Cb, int M, int K, int N,
    const float* __restrict__ bias, float alpha, int relu,
    unsigned* smp)
{
    const int t = threadIdx.x;
    const int lane = t & 31, wid = t >> 5;
    const int warpM = wid >> 2, warpN = wid & 3;
    const int bm = blockIdx.y << 7, bn = blockIdx.x << 7;

    float acc[4][4][4];
#pragma unroll
    for (int a = 0; a < 4; ++a)
#pragma unroll
        for (int b = 0; b < 4; ++b)
#pragma unroll
            for (int c = 0; c < 4; ++c) acc[a][b][c] = 0.f;

    const int amt = t >> 5, als = t & 31;
    const int amo = (amt << 4) + (als >> 2);
    const int ako = (als & 3) << 1;
    int bno[2], bko[2];
#pragma unroll
    for (int i = 0; i < 2; ++i) {
        int s = t + (i << 8), nt = s >> 5, ls = s & 31;
        bno[i] = (nt << 3) + (ls >> 2);
        bko[i] = (ls & 3) << 1;
    }

    float2 pa[4];
    float2 pb[2][2];

    auto loadG = [&](int k0) {
        const float* ap = W + (size_t)(bm + amo) * K + (k0 + ako);
        pa[0] = *(const float2*)ap;
        pa[1] = *(const float2*)(ap + (size_t)8 * K);
        pa[2] = *(const float2*)(ap + 8);
        pa[3] = *(const float2*)(ap + (size_t)8 * K + 8);
#pragma unroll
        for (int i = 0; i < 2; ++i) {
            const float* bp = Xb + (size_t)(k0 + bko[i]) * N + bn + bno[i];
            pb[i][0] = make_float2(bp[0], bp[N]);
            pb[i][1] = make_float2(bp[(size_t)8 * N], bp[(size_t)9 * N]);
        }
    };

    auto storeS = [&](int buf) {
        unsigned* Ah = smp + buf * 4096;
        unsigned* Al = smp + buf * 4096 + 1024;
        unsigned* Bh = smp + buf * 4096 + 2048;
        unsigned* Bl = smp + buf * 4096 + 3072;
        {
            unsigned h[4], l[4];
#pragma unroll
            for (int r = 0; r < 4; ++r) {
                float hx = bfhi(pa[r].x), hy = bfhi(pa[r].y);
                h[r] = bf2pack(pa[r].x, pa[r].y);
                l[r] = bf2pack(pa[r].x - hx, pa[r].y - hy);
            }
            *(uint4*)&Ah[t * 4] = make_uint4(h[0], h[1], h[2], h[3]);
            *(uint4*)&Al[t * 4] = make_uint4(l[0], l[1], l[2], l[3]);
        }
#pragma unroll
        for (int i = 0; i < 2; ++i) {
            int s = t + (i << 8);
            float hx = bfhi(pb[i][0].x), hy = bfhi(pb[i][0].y);
            unsigned h0 = bf2pack(pb[i][0].x, pb[i][0].y);
            unsigned l0 = bf2pack(pb[i][0].x - hx, pb[i][0].y - hy);
            hx = bfhi(pb[i][1].x); hy = bfhi(pb[i][1].y);
            unsigned h1 = bf2pack(pb[i][1].x, pb[i][1].y);
            unsigned l1 = bf2pack(pb[i][1].x - hx, pb[i][1].y - hy);
            *(uint2*)&Bh[s * 2] = make_uint2(h0, h1);
            *(uint2*)&Bl[s * 2] = make_uint2(l0, l1);
        }
    };

    auto compute = [&](int buf) {
        const unsigned* Ah = smp + buf * 4096;
        const unsigned* Al = smp + buf * 4096 + 1024;
        const unsigned* Bh = smp + buf * 4096 + 2048;
        const unsigned* Bl = smp + buf * 4096 + 3072;
        uint4 ah[4], alr[4];
#pragma unroll
        for (int mt = 0; mt < 4; ++mt) {
            int idx = (warpM * 4 + mt) * 32 + lane;
            ah[mt]  = *(const uint4*)&Ah[idx * 4];
            alr[mt] = *(const uint4*)&Al[idx * 4];
        }
#pragma unroll
        for (int nt = 0; nt < 4; ++nt) {
            int idx = (warpN * 4 + nt) * 32 + lane;
            uint2 bh = *(const uint2*)&Bh[idx * 2];
            uint2 bl = *(const uint2*)&Bl[idx * 2];
#pragma unroll
            for (int mt = 0; mt < 4; ++mt) {
                float* c = acc[mt][nt];
                mma_bf16(c[0], c[1], c[2], c[3],
                         ah[mt].x, ah[mt].y, ah[mt].z, ah[mt].w, bh.x, bh.y);
                mma_bf16(c[0], c[1], c[2], c[3],
                         ah[mt].x, ah[mt].y, ah[mt].z, ah[mt].w, bl.x, bl.y);
                mma_bf16(c[0], c[1], c[2], c[3],
                         alr[mt].x, alr[mt].y, alr[mt].z, alr[mt].w, bh.x, bh.y);
            }
        }
    };

    const int kiters = K >> 4;
    loadG(0);
    storeS(0);
    __syncthreads();
    for (int it = 0; it < kiters; ++it) {
        const int cur = it & 1;
        if (it + 1 < kiters) loadG((it + 1) << 4);
        compute(cur);
        if (it + 1 < kiters) storeS(cur ^ 1);
        __syncthreads();
    }

    const int r = lane >> 2, j = lane & 3;
#pragma unroll
    for (int mt = 0; mt < 4; ++mt) {
        const int m0 = bm + warpM * 64 + mt * 16 + r;
        const float bv0 = bias ? bias[m0] : 0.f;
        const float bv1 = bias ? bias[m0 + 8] : 0.f;
#pragma unroll
        for (int nt = 0; nt < 4; ++nt) {
            const int n = bn + warpN * 32 + nt * 8 + j * 2;
            const float* c = acc[mt][nt];
            float r0 = alpha * c[0] + bv0, r1 = alpha * c[1] + bv0;
            float r2 = alpha * c[2] + bv1, r3 = alpha * c[3] + bv1;
            if (relu) {
                r0 = fmaxf(r0, 0.f); r1 = fmaxf(r1, 0.f);
                r2 = fmaxf(r2, 0.f); r3 = fmaxf(r3, 0.f);
            }
            *(float2*)&Cb[(size_t)m0 * N + n] = make_float2(r0, r1);
            *(float2*)&Cb[(size_t)(m0 + 8) * N + n] = make_float2(r2, r3);
        }
    }
}

__global__ __launch_bounds__(256) void gemm_tc(
    const float* __restrict__ W, const float* __restrict__ X,
    float* __restrict__ C, int M, int K, int N,
    const float* __restrict__ bias, float alpha, int relu)
{
    extern __shared__ __align__(16) unsigned smp[];
    gemm_body(W, X + (size_t)blockIdx.z * K * N, C + (size_t)blockIdx.z * M * N,
              M, K, N, bias, alpha, relu, smp);
}

__global__ __launch_bounds__(256) void gemm_qkv(
    const float* __restrict__ Wq_l, const float* __restrict__ Wk_l,
    const float* __restrict__ Wv_l, const float* __restrict__ Wq_r,
    const float* __restrict__ Wk_r, const float* __restrict__ Wv_r,
    const float* __restrict__ left, const float* __restrict__ right,
    float* ql, float* kl, float* vl, float* qr, float* kr, float* vr,
    float qscale)
{
    extern __shared__ __align__(16) unsigned smp[];
    const int z = blockIdx.z, which = z >> 1, b = z & 1;
    const float* Ws[6] = {Wq_l, Wk_l, Wv_l, Wq_r, Wk_r, Wv_r};
    float*       Cs[6] = {ql, kl, vl, qr, kr, vr};
    const float* X = (which < 3) ? left : right;
    const float alpha = (which == 0 || which == 3) ? qscale : 1.f;
    gemm_body(Ws[which], X + (size_t)b * EE * SS, Cs[which] + (size_t)b * EE * SS,
              EE, EE, SS, nullptr, alpha, 0, smp);
}

// ---------------------------------------------------------------------------
// Tensor-core flash attention (causal), split-bf16 3-product, FA2 fragment
// chaining. Scores are in log2 domain (log2e folded into q projection), so
// softmax uses exp2p (FMA pipe, no MUFU).
//
// Block: 128 q rows of one (b,h,path); 256 threads = 8 warps; warp owns 16 q.
// Key tile 64. Warp tile QK: m16 x (8 nt x n8) x k16 over d; PV: m16 x (8 d-
// tiles) x k16 over t. C frags of QK reused directly as A frags of PV.
//
// SMEM (words): Qh[4096] Ql[4096] Kh[2048] Kl[2048] Vh[2048] Vl[2048] = 64KB
// ---------------------------------------------------------------------------
#define ATTN_SMEM (16384 * 4)

__global__ __launch_bounds__(256, 2) void attn_mma(
    const float* __restrict__ Qlp, const float* __restrict__ Klp,
    const float* __restrict__ Vlp, float* __restrict__ Olp,
    const float* __restrict__ Qrp, const float* __restrict__ Krp,
    const float* __restrict__ Vrp, float* __restrict__ Orp)
{
    extern __shared__ __align__(16) unsigned smw[];
    unsigned* Qh = smw;            // 4096
    unsigned* Qlo = smw + 4096;    // 4096
    unsigned* Kh = smw + 8192;     // 2048
    unsigned* Klo = smw + 10240;   // 2048
    unsigned* Vh = smw + 12288;    // 2048
    unsigned* Vlo = smw + 14336;   // 2048

    const int tid = threadIdx.x;
    const int lane = tid & 31, w = tid >> 5;
    const int path = blockIdx.z >> 1;
    const int bz = blockIdx.z & 1;
    const float* Q = path ? Qrp : Qlp;
    const float* Kg = path ? Krp : Klp;
    const float* V = path ? Vrp : Vlp;
    float* O = path ? Orp : Olp;

    const int qt = (gridDim.x - 1) - blockIdx.x;   // heavy tiles first
    const int q0 = qt << 7;
    const size_t base = ((size_t)bz * EE + (size_t)blockIdx.y * DD) * SS;
    const float* Qp = Q + base;
    const float* Kp = Kg + base;
    const float* Vp = V + base;

    // ---- Q fragments (once per block): slot = ((wq*4+kc)*32+lane), 4 regs ----
#pragma unroll
    for (int i = 0; i < 4; ++i) {
        int s = tid + (i << 8);
        int ls = s & 31, kc = (s >> 5) & 3, wq = s >> 7;
        int qr_ = q0 + (wq << 4) + (ls >> 2);
        int d0 = (kc << 4) + ((ls & 3) << 1);
        const float* p00 = Qp + (size_t)d0 * SS + qr_;
        float f0a = p00[0],              f0b = p00[SS];               // r0: (q, d0,d0+1)
        float f1a = p00[8],              f1b = p00[SS + 8];           // r1: (q+8, d0,d0+1)
        float f2a = p00[(size_t)8 * SS], f2b = p00[(size_t)9 * SS];   // r2: (q, d0+8,+9)
        float f3a = p00[(size_t)8 * SS + 8], f3b = p00[(size_t)9 * SS + 8]; // r3
        unsigned h0 = bf2pack(f0a, f0b), h1 = bf2pack(f1a, f1b);
        unsigned h2 = bf2pack(f2a, f2b), h3 = bf2pack(f3a, f3b);
        unsigned l0 = bf2pack(f0a - bfhi(f0a), f0b - bfhi(f0b));
        unsigned l1 = bf2pack(f1a - bfhi(f1a), f1b - bfhi(f1b));
        unsigned l2 = bf2pack(f2a - bfhi(f2a), f2b - bfhi(f2b));
        unsigned l3 = bf2pack(f3a - bfhi(f3a), f3b - bfhi(f3b));
        *(uint4*)&Qh[s * 4]  = make_uint4(h0, h1, h2, h3);
        *(uint4*)&Qlo[s * 4] = make_uint4(l0, l1, l2, l3);
    }

    float o[8][4];
#pragma unroll
    for (int i = 0; i < 8; ++i)
#pragma unroll
        for (int j = 0; j < 4; ++j) o[i][j] = 0.f;
    float m0 = -1e30f, m1 = -1e30f, l0s = 0.f, l1s = 0.f;

    const int qg = q0 + (w << 4) + (lane >> 2);   // this thread's row (and +8)
    const int ntile = qt * 2 + 2;

    for (int kt = 0; kt < ntile; ++kt) {
        const int t0 = kt << 6;
        __syncthreads();
        // ---- K fragments: slot=((nt*4+kc)*32+lane), 2 regs ----
#pragma unroll
        for (int i = 0; i < 4; ++i) {
            int s = tid + (i << 8);
            int ls = s & 31, kc = (s >> 5) & 3, nt = s >> 7;
            int tt = t0 + (nt << 3) + (ls >> 2);
            int d0 = (kc << 4) + ((ls & 3) << 1);
            const float* p00 = Kp + (size_t)d0 * SS + tt;
            float f0a = p00[0], f0b = p00[SS];
            float f1a = p00[(size_t)8 * SS], f1b = p00[(size_t)9 * SS];
            *(uint2*)&Kh[s * 2] = make_uint2(bf2pack(f0a, f0b), bf2pack(f1a, f1b));
            *(uint2*)&Klo[s * 2] = make_uint2(
                bf2pack(f0a - bfhi(f0a), f0b - bfhi(f0b)),
                bf2pack(f1a - bfhi(f1a), f1b - bfhi(f1b)));
        }
        // ---- V fragments: slot=((ndt*4+tc)*32+lane), 2 regs ----
#pragma unroll
        for (int i = 0; i < 4; ++i) {
            int s = tid + (i << 8);
            int ls = s & 31, tc = (s >> 5) & 3, ndt = s >> 7;
            int d = (ndt << 3) + (ls >> 2);
            int tt = t0 + (tc << 4) + ((ls & 3) << 1);
            const float* p00 = Vp + (size_t)d * SS + tt;
            float2 v0 = *(const float2*)p00;
            float2 v1 = *(const float2*)(p00 + 8);
            *(uint2*)&Vh[s * 2] = make_uint2(bf2pack(v0.x, v0.y), bf2pack(v1.x, v1.y));
            *(uint2*)&Vlo[s * 2] = make_uint2(
                bf2pack(v0.x - bfhi(v0.x), v0.y - bfhi(v0.y)),
                bf2pack(v1.x - bfhi(v1.x), v1.y - bfhi(v1.y)));
        }
        __syncthreads();

        // ---- QK^T: sreg[nt][4], rows (g, g+8), cols (2c, 2c+1) of t-tile nt ----
        float sreg[8][4];
#pragma unroll
        for (int i = 0; i < 8; ++i)
#pragma unroll
            for (int j = 0; j < 4; ++j) sreg[i][j] = 0.f;
#pragma unroll
        for (int kc = 0; kc < 4; ++kc) {
            int ai = ((w * 4 + kc) * 32 + lane);
            uint4 ah = *(const uint4*)&Qh[ai * 4];
            uint4 al = *(const uint4*)&Qlo[ai * 4];
#pragma unroll
            for (int nt = 0; nt < 8; ++nt) {
                int bi = ((nt * 4 + kc) * 32 + lane);
                uint2 bh = *(const uint2*)&Kh[bi * 2];
                uint2 bl = *(const uint2*)&Klo[bi * 2];
                float* c = sreg[nt];
                mma_bf16(c[0], c[1], c[2], c[3], ah.x, ah.y, ah.z, ah.w, bh.x, bh.y);
                mma_bf16(c[0], c[1], c[2], c[3], ah.x, ah.y, ah.z, ah.w, bl.x, bl.y);
                mma_bf16(c[0], c[1], c[2], c[3], al.x, al.y, al.z, al.w, bh.x, bh.y);
            }
        }

        // ---- causal mask + online softmax (log2 domain) ----
        float mx0 = m0, mx1 = m1;
#pragma unroll
        for (int nt = 0; nt < 8; ++nt) {
            int tb = t0 + (nt << 3) + ((lane & 3) << 1);
            if (tb > qg)     sreg[nt][0] = -1e30f;
            if (tb + 1 > qg) sreg[nt][1] = -1e30f;
            if (tb > qg + 8)     sreg[nt][2] = -1e30f;
            if (tb + 1 > qg + 8) sreg[nt][3] = -1e30f;
            mx0 = fmaxf(mx0, fmaxf(sreg[nt][0], sreg[nt][1]));
            mx1 = fmaxf(mx1, fmaxf(sreg[nt][2], sreg[nt][3]));
        }
        mx0 = fmaxf(mx0, __shfl_xor_sync(0xffffffffu, mx0, 1));
        mx0 = fmaxf(mx0, __shfl_xor_sync(0xffffffffu, mx0, 2));
        mx1 = fmaxf(mx1, __shfl_xor_sync(0xffffffffu, mx1, 1));
        mx1 = fmaxf(mx1, __shfl_xor_sync(0xffffffffu, mx1, 2));
        float corr0 = exp2p(m0 - mx0), corr1 = exp2p(m1 - mx1);
        m0 = mx0; m1 = mx1;
        l0s *= corr0; l1s *= corr1;
#pragma unroll
        for (int nt = 0; nt < 8; ++nt) {
            o[nt][0] *= corr0; o[nt][1] *= corr0;
            o[nt][2] *= corr1; o[nt][3] *= corr1;
        }
        float ls0 = 0.f, ls1 = 0.f;
#pragma unroll
        for (int nt = 0; nt < 8; ++nt) {
            float p0 = exp2p(sreg[nt][0] - mx0);
            float p1 = exp2p(sreg[nt][1] - mx0);
            float p2 = exp2p(sreg[nt][2] - mx1);
            float p3 = exp2p(sreg[nt][3] - mx1);
            sreg[nt][0] = p0; sreg[nt][1] = p1;
            sreg[nt][2] = p2; sreg[nt][3] = p3;
            ls0 += p0 + p1; ls1 += p2 + p3;
        }
        ls0 += __shfl_xor_sync(0xffffffffu, ls0, 1);
        ls0 += __shfl_xor_sync(0xffffffffu, ls0, 2);
        ls1 += __shfl_xor_sync(0xffffffffu, ls1, 1);
        ls1 += __shfl_xor_sync(0xffffffffu, ls1, 2);
        l0s += ls0; l1s += ls1;

        // ---- P V: C frags of QK are A frags of PV (tiles 2j, 2j+1 -> chunk j) ----
#pragma unroll
        for (int j = 0; j < 4; ++j) {
            float* pA = sreg[2 * j];
            float* pB = sreg[2 * j + 1];
            unsigned ah0 = bf2pack(pA[0], pA[1]);
            unsigned ah1 = bf2pack(pA[2], pA[3]);
            unsigned ah2 = bf2pack(pB[0], pB[1]);
            unsigned ah3 = bf2pack(pB[2], pB[3]);
            unsigned al0 = bf2pack(pA[0] - bfhi(pA[0]), pA[1] - bfhi(pA[1]));
            unsigned al1 = bf2pack(pA[2] - bfhi(pA[2]), pA[3] - bfhi(pA[3]));
            unsigned al2 = bf2pack(pB[0] - bfhi(pB[0]), pB[1] - bfhi(pB[1]));
            unsigned al3 = bf2pack(pB[2] - bfhi(pB[2]), pB[3] - bfhi(pB[3]));
#pragma unroll
            for (int nt = 0; nt < 8; ++nt) {
                int bi = ((nt * 4 + j) * 32 + lane);
                uint2 bh = *(const uint2*)&Vh[bi * 2];
                uint2 bl = *(const uint2*)&Vlo[bi * 2];
                float* c = o[nt];
                mma_bf16(c[0], c[1], c[2], c[3], ah0, ah1, ah2, ah3, bh.x, bh.y);
                mma_bf16(c[0], c[1], c[2], c[3], ah0, ah1, ah2, ah3, bl.x, bl.y);
                mma_bf16(c[0], c[1], c[2], c[3], al0, al1, al2, al3, bh.x, bh.y);
            }
        }
    }

    // ---- epilogue ----
    const float inv0 = 1.f / l0s, inv1 = 1.f / l1s;
    float* Op = O + base;
#pragma unroll
    for (int nt = 0; nt < 8; ++nt) {
        int d = (nt << 3) + ((lane & 3) << 1);
        Op[(size_t)d * SS + qg]       = o[nt][0] * inv0;
        Op[(size_t)(d + 1) * SS + qg] = o[nt][1] * inv0;
        Op[(size_t)d * SS + qg + 8]       = o[nt][2] * inv1;
        Op[(size_t)(d + 1) * SS + qg + 8] = o[nt][3] * inv1;
    }
}

// ---------------------------------------------------------------------------
// lambda = exp(sum lam_q_l*lam_k_l) - exp(sum lam_q_r*lam_k_r) + 0.1
// ---------------------------------------------------------------------------
__global__ void lam_kernel(const float* __restrict__ ql, const float* __restrict__ kl,
                           const float* __restrict__ qr, const float* __restrict__ kr)
{
    const int t = threadIdx.x;
    float a = ql[t] * kl[t] + ql[t + 32] * kl[t + 32];
    float b = qr[t] * kr[t] + qr[t + 32] * kr[t + 32];
#pragma unroll
    for (int off = 16; off > 0; off >>= 1) {
        a += __shfl_xor_sync(0xffffffffu, a, off);
        b += __shfl_xor_sync(0xffffffffu, b, off);
    }
    if (t == 0) g_lam = expf(a) - expf(b) + 0.1f;
}

// ---------------------------------------------------------------------------
// combined = attn_l - lam*attn_r; LayerNorm over E (biased var, eps 1e-5).
// ---------------------------------------------------------------------------
__global__ __launch_bounds__(512) void ln_kernel(
    const float* __restrict__ al, const float* __restrict__ ar,
    const float* __restrict__ gg, const float* __restrict__ bbv,
    float* __restrict__ out)
{
    __shared__ float ps[16][32], pq[16][32], smu[32], srs[32];
    const int tid = threadIdx.x;
    const int ty = tid >> 5, sl = tid & 31;
    const int b = blockIdx.x >> 6;
    const int s = ((blockIdx.x & 63) << 5) + sl;
    const float lam = g_lam;
    const size_t col = (size_t)b * EE * SS + s;
    const int e0 = ty << 6;

    float sum = 0.f, sq = 0.f;
    for (int e = e0; e < e0 + 64; ++e) {
        size_t idx = col + (size_t)e * SS;
        float c = al[idx] - lam * ar[idx];
        sum += c; sq += c * c;
    }
    ps[ty][sl] = sum; pq[ty][sl] = sq;
    __syncthreads();
    if (ty == 0) {
        float ts = 0.f, tq = 0.f;
#pragma unroll
        for (int r = 0; r < 16; ++r) { ts += ps[r][sl]; tq += pq[r][sl]; }
        float mu = ts * (1.f / EE);
        float var = tq * (1.f / EE) - mu * mu;
        smu[sl] = mu;
        srs[sl] = rsqrtf(var + 1e-5f);
    }
    __syncthreads();
    const float mu = smu[sl], rs = srs[sl];
    for (int e = e0; e < e0 + 64; ++e) {
        size_t idx = col + (size_t)e * SS;
        float c = al[idx] - lam * ar[idx];
        out[idx] = (c - mu) * rs * gg[e] + bbv[e];
    }
}

// ---------------------------------------------------------------------------
// Launch
// ---------------------------------------------------------------------------
static float* sym_addr(const void* symbol)
{
    void* p = nullptr;
    cudaGetSymbolAddress(&p, symbol);
    return (float*)p;
}

extern "C" void kernel_launch(void* const* d_in, const int* in_sizes, int n_in,
                              void* d_out, int out_size)
{
    const float* left  = (const float*)d_in[0];
    const float* right = (const float*)d_in[1];
    const float* Wq_l  = (const float*)d_in[2];
    const float* Wk_l  = (const float*)d_in[3];
    const float* Wv_l  = (const float*)d_in[4];
    const float* Wq_r  = (const float*)d_in[5];
    const float* Wk_r  = (const float*)d_in[6];
    const float* Wv_r  = (const float*)d_in[7];
    const float* Wo    = (const float*)d_in[8];
    const float* lql   = (const float*)d_in[9];
    const float* lkl   = (const float*)d_in[10];
    const float* lqr   = (const float*)d_in[11];
    const float* lkr   = (const float*)d_in[12];
    const float* ln_g  = (const float*)d_in[13];
    const float* ln_b  = (const float*)d_in[14];
    const float* W1    = (const float*)d_in[15];
    const float* b1    = (const float*)d_in[16];
    const float* W2    = (const float*)d_in[17];
    const float* b2    = (const float*)d_in[18];
    float* out = (float*)d_out;

    float* ql = sym_addr(g_ql); float* kl = sym_addr(g_kl); float* vl = sym_addr(g_vl);
    float* qr = sym_addr(g_qr); float* kr = sym_addr(g_kr); float* vr = sym_addr(g_vr);
    float* al = sym_addr(g_al); float* ar = sym_addr(g_ar);
    float* lno = sym_addr(g_lnout);
    float* h1 = sym_addr(g_h1);
    float* wf = sym_addr(g_wf);

    // D^-0.5 * log2(e): scores come out in log2 domain (softmax-invariant)
    const float qscale = 0.125f * 1.4426950408889634f;

    cudaFuncSetAttribute(gemm_tc, cudaFuncAttributeMaxDynamicSharedMemorySize,
                         GEMM_SMEM);
    cudaFuncSetAttribute(gemm_qkv, cudaFuncAttributeMaxDynamicSharedMemorySize,
                         GEMM_SMEM);
    cudaFuncSetAttribute(attn_mma, cudaFuncAttributeMaxDynamicSharedMemorySize,
                         ATTN_SMEM);

    dim3 blk(256);
    dim3 gp(SS / 128, EE / 128, BB);         // (16, 8, 2)
    dim3 gp1(SS / 128, (2 * EE) / 128, BB);  // (16, 16, 2)
    dim3 gpw(EE / 128, (2 * EE) / 128, 1);   // Wf = W1 @ Wo precompute
    dim3 gq(SS / 128, EE / 128, 6 * BB);     // all 6 QKV GEMMs

    // Wf precompute early (independent of activations)
    gemm_tc<<<gpw, blk, GEMM_SMEM>>>(W1, Wo, wf, 2 * EE, EE, EE, nullptr, 1.f, 0);

    // QKV projections: one launch, 1536 blocks
    gemm_qkv<<<gq, blk, GEMM_SMEM>>>(Wq_l, Wk_l, Wv_l, Wq_r, Wk_r, Wv_r,
                                     left, right, ql, kl, vl, qr, kr, vr, qscale);

    // attention: both paths in one launch (z = path*2 + b)
    dim3 ga(SS / 128, HH, 2 * BB);           // (16, 16, 4)
    attn_mma<<<ga, 256, ATTN_SMEM>>>(ql, kl, vl, al, qr, kr, vr, ar);

    // lambda, combine + LN
    lam_kernel<<<1, 32>>>(lql, lkl, lqr, lkr);
    ln_kernel<<<BB * (SS / 32), 512>>>(al, ar, ln_g, ln_b, lno);

    // fused (W1@Wo) + relu, then W2 straight into d_out ([B,E,S])
    gemm_tc<<<gp1, blk, GEMM_SMEM>>>(wf, lno, h1,  2 * EE, EE,     SS, b1, 1.f, 1);
    gemm_tc<<<gp,  blk, GEMM_SMEM>>>(W2, h1,  out, EE,     2 * EE, SS, b2, 1.f, 0);
}

// round 8
// speedup vs baseline: 2.7850x; 1.0214x over previous
#include <cuda_runtime.h>
#include <cuda_bf16.h>
#include <math.h>

// Problem constants
#define BB 2
#define EE 1024
#define SS 2048
#define HH 16
#define DD 64
#define BES (BB*EE*SS)          // 4,194,304 elements

// ---------------------------------------------------------------------------
// Scratch (device globals; no runtime allocation allowed)
// ---------------------------------------------------------------------------
__device__ float g_ql[BES], g_kl[BES], g_vl[BES];
__device__ float g_qr[BES], g_kr[BES], g_vr[BES];
__device__ float g_al[BES], g_ar[BES];
__device__ float g_lnout[BES];
__device__ float g_h1[2 * BES];
__device__ float g_wf[2 * EE * EE];     // fused W1@Wo
__device__ float g_lam;

// ---------------------------------------------------------------------------
// bf16 split helpers
// ---------------------------------------------------------------------------
__device__ __forceinline__ unsigned bf2pack(float x, float y) {
    __nv_bfloat162 h = __floats2bfloat162_rn(x, y);
    return *reinterpret_cast<unsigned*>(&h);
}
__device__ __forceinline__ float bfhi(float x) {
    return __bfloat162float(__float2bfloat16(x));
}
__device__ __forceinline__ void mma_bf16(
    float& c0, float& c1, float& c2, float& c3,
    unsigned a0, unsigned a1, unsigned a2, unsigned a3,
    unsigned b0, unsigned b1)
{
    asm("mma.sync.aligned.m16n8k16.row.col.f32.bf16.bf16.f32 "
        "{%0,%1,%2,%3}, {%4,%5,%6,%7}, {%8,%9}, {%0,%1,%2,%3};"
        : "+f"(c0), "+f"(c1), "+f"(c2), "+f"(c3)
        : "r"(a0), "r"(a1), "r"(a2), "r"(a3), "r"(b0), "r"(b1));
}

// exp2 via FMA-pipe polynomial (degree-5 Taylor on f in [-0.5,0.5], rel ~2e-6).
__device__ __forceinline__ float exp2p(float z) {
    z = fmaxf(z, -100.f);
    float n = rintf(z);
    float f = z - n;
    float p = 0.00133335581f;
    p = fmaf(p, f, 0.00961812911f);
    p = fmaf(p, f, 0.05550410866f);
    p = fmaf(p, f, 0.24022650696f);
    p = fmaf(p, f, 0.69314718056f);
    p = fmaf(p, f, 1.0f);
    float sc = __int_as_float(((int)n + 127) << 23);
    return p * sc;
}

// ---------------------------------------------------------------------------
// Tensor-core GEMM body (3-product split-bf16 m16n8k16), double-buffered,
// two-pass compute (A-hi pass then A-lo pass) to fit 2 blocks/SM in regs.
// C[m][n] = relu?(alpha * sum_k W[m][k] * Xb[k][n] + bias[m])
// Block tile 128x128, BK=16, 256 threads = 8 warps (2 warpM x 4 warpN).
// Per-buffer word layout: Ah[0..1023] Al[1024..2047] Bh[2048..3071] Bl[3072..4095]
// ---------------------------------------------------------------------------
#define GEMM_SMEM (2 * 4096 * 4)

__device__ __forceinline__ void gemm_body(
    const float* __restrict__ W, const float* __restrict__ Xb,
    float* __restrict__ Cb, int M, int K, int N,
    const float* __restrict__ bias, float alpha, int relu,
    unsigned* smp)
{
    const int t = threadIdx.x;
    const int lane = t & 31, wid = t >> 5;
    const int warpM = wid >> 2, warpN = wid & 3;
    const int bm = blockIdx.y << 7, bn = blockIdx.x << 7;

    float acc[4][4][4];
#pragma unroll
    for (int a = 0; a < 4; ++a)
#pragma unroll
        for (int b = 0; b < 4; ++b)
#pragma unroll
            for (int c = 0; c < 4; ++c) acc[a][b][c] = 0.f;

    const int amt = t >> 5, als = t & 31;
    const int amo = (amt << 4) + (als >> 2);
    const int ako = (als & 3) << 1;
    int bno[2], bko[2];
#pragma unroll
    for (int i = 0; i < 2; ++i) {
        int s = t + (i << 8), nt = s >> 5, ls = s & 31;
        bno[i] = (nt << 3) + (ls >> 2);
        bko[i] = (ls & 3) << 1;
    }

    float2 pa[4];
    float2 pb[2][2];

    auto loadG = [&](int k0) {
        const float* ap = W + (size_t)(bm + amo) * K + (k0 + ako);
        pa[0] = *(const float2*)ap;
        pa[1] = *(const float2*)(ap + (size_t)8 * K);
        pa[2] = *(const float2*)(ap + 8);
        pa[3] = *(const float2*)(ap + (size_t)8 * K + 8);
#pragma unroll
        for (int i = 0; i < 2; ++i) {
            const float* bp = Xb + (size_t)(k0 + bko[i]) * N + bn + bno[i];
            pb[i][0] = make_float2(bp[0], bp[N]);
            pb[i][1] = make_float2(bp[(size_t)8 * N], bp[(size_t)9 * N]);
        }
    };

    auto storeS = [&](int buf) {
        unsigned* Ah = smp + buf * 4096;
        unsigned* Al = smp + buf * 4096 + 1024;
        unsigned* Bh = smp + buf * 4096 + 2048;
        unsigned* Bl = smp + buf * 4096 + 3072;
        {
            unsigned h[4], l[4];
#pragma unroll
            for (int r = 0; r < 4; ++r) {
                float hx = bfhi(pa[r].x), hy = bfhi(pa[r].y);
                h[r] = bf2pack(pa[r].x, pa[r].y);
                l[r] = bf2pack(pa[r].x - hx, pa[r].y - hy);
            }
            *(uint4*)&Ah[t * 4] = make_uint4(h[0], h[1], h[2], h[3]);
            *(uint4*)&Al[t * 4] = make_uint4(l[0], l[1], l[2], l[3]);
        }
#pragma unroll
        for (int i = 0; i < 2; ++i) {
            int s = t + (i << 8);
            float hx = bfhi(pb[i][0].x), hy = bfhi(pb[i][0].y);
            unsigned h0 = bf2pack(pb[i][0].x, pb[i][0].y);
            unsigned l0 = bf2pack(pb[i][0].x - hx, pb[i][0].y - hy);
            hx = bfhi(pb[i][1].x); hy = bfhi(pb[i][1].y);
            unsigned h1 = bf2pack(pb[i][1].x, pb[i][1].y);
            unsigned l1 = bf2pack(pb[i][1].x - hx, pb[i][1].y - hy);
            *(uint2*)&Bh[s * 2] = make_uint2(h0, h1);
            *(uint2*)&Bl[s * 2] = make_uint2(l0, l1);
        }
    };

    // Two-pass compute: pass1 = Ah x (Bh, Bl); pass2 = Al x Bh.
    // Only one set of A fragments resident at a time (saves ~16 regs).
    auto compute = [&](int buf) {
        const unsigned* Ah = smp + buf * 4096;
        const unsigned* Al = smp + buf * 4096 + 1024;
        const unsigned* Bh = smp + buf * 4096 + 2048;
        const unsigned* Bl = smp + buf * 4096 + 3072;
        uint4 af[4];
#pragma unroll
        for (int mt = 0; mt < 4; ++mt)
            af[mt] = *(const uint4*)&Ah[((warpM * 4 + mt) * 32 + lane) * 4];
#pragma unroll
        for (int nt = 0; nt < 4; ++nt) {
            int idx = (warpN * 4 + nt) * 32 + lane;
            uint2 bh = *(const uint2*)&Bh[idx * 2];
            uint2 bl = *(const uint2*)&Bl[idx * 2];
#pragma unroll
            for (int mt = 0; mt < 4; ++mt) {
                float* c = acc[mt][nt];
                mma_bf16(c[0], c[1], c[2], c[3],
                         af[mt].x, af[mt].y, af[mt].z, af[mt].w, bh.x, bh.y);
                mma_bf16(c[0], c[1], c[2], c[3],
                         af[mt].x, af[mt].y, af[mt].z, af[mt].w, bl.x, bl.y);
            }
        }
#pragma unroll
        for (int mt = 0; mt < 4; ++mt)
            af[mt] = *(const uint4*)&Al[((warpM * 4 + mt) * 32 + lane) * 4];
#pragma unroll
        for (int nt = 0; nt < 4; ++nt) {
            int idx = (warpN * 4 + nt) * 32 + lane;
            uint2 bh = *(const uint2*)&Bh[idx * 2];
#pragma unroll
            for (int mt = 0; mt < 4; ++mt) {
                float* c = acc[mt][nt];
                mma_bf16(c[0], c[1], c[2], c[3],
                         af[mt].x, af[mt].y, af[mt].z, af[mt].w, bh.x, bh.y);
            }
        }
    };

    const int kiters = K >> 4;
    loadG(0);
    storeS(0);
    __syncthreads();
    for (int it = 0; it < kiters; ++it) {
        const int cur = it & 1;
        if (it + 1 < kiters) loadG((it + 1) << 4);
        compute(cur);
        if (it + 1 < kiters) storeS(cur ^ 1);
        __syncthreads();
    }

    const int r = lane >> 2, j = lane & 3;
#pragma unroll
    for (int mt = 0; mt < 4; ++mt) {
        const int m0 = bm + warpM * 64 + mt * 16 + r;
        const float bv0 = bias ? bias[m0] : 0.f;
        const float bv1 = bias ? bias[m0 + 8] : 0.f;
#pragma unroll
        for (int nt = 0; nt < 4; ++nt) {
            const int n = bn + warpN * 32 + nt * 8 + j * 2;
            const float* c = acc[mt][nt];
            float r0 = alpha * c[0] + bv0, r1 = alpha * c[1] + bv0;
            float r2 = alpha * c[2] + bv1, r3 = alpha * c[3] + bv1;
            if (relu) {
                r0 = fmaxf(r0, 0.f); r1 = fmaxf(r1, 0.f);
                r2 = fmaxf(r2, 0.f); r3 = fmaxf(r3, 0.f);
            }
            *(float2*)&Cb[(size_t)m0 * N + n] = make_float2(r0, r1);
            *(float2*)&Cb[(size_t)(m0 + 8) * N + n] = make_float2(r2, r3);
        }
    }
}

__global__ __launch_bounds__(256, 2) void gemm_tc(
    const float* __restrict__ W, const float* __restrict__ X,
    float* __restrict__ C, int M, int K, int N,
    const float* __restrict__ bias, float alpha, int relu)
{
    extern __shared__ __align__(16) unsigned smp[];
    gemm_body(W, X + (size_t)blockIdx.z * K * N, C + (size_t)blockIdx.z * M * N,
              M, K, N, bias, alpha, relu, smp);
}

__global__ __launch_bounds__(256, 2) void gemm_qkv(
    const float* __restrict__ Wq_l, const float* __restrict__ Wk_l,
    const float* __restrict__ Wv_l, const float* __restrict__ Wq_r,
    const float* __restrict__ Wk_r, const float* __restrict__ Wv_r,
    const float* __restrict__ left, const float* __restrict__ right,
    float* ql, float* kl, float* vl, float* qr, float* kr, float* vr,
    float qscale)
{
    extern __shared__ __align__(16) unsigned smp[];
    const int z = blockIdx.z, which = z >> 1, b = z & 1;
    const float* Ws[6] = {Wq_l, Wk_l, Wv_l, Wq_r, Wk_r, Wv_r};
    float*       Cs[6] = {ql, kl, vl, qr, kr, vr};
    const float* X = (which < 3) ? left : right;
    const float alpha = (which == 0 || which == 3) ? qscale : 1.f;
    gemm_body(Ws[which], X + (size_t)b * EE * SS, Cs[which] + (size_t)b * EE * SS,
              EE, EE, SS, nullptr, alpha, 0, smp);
}

// ---------------------------------------------------------------------------
// Tensor-core flash attention (causal), split-bf16 3-product, FA2 fragment
// chaining, log2-domain softmax via exp2p. (unchanged from passing round 7)
// ---------------------------------------------------------------------------
#define ATTN_SMEM (16384 * 4)

__global__ __launch_bounds__(256, 2) void attn_mma(
    const float* __restrict__ Qlp, const float* __restrict__ Klp,
    const float* __restrict__ Vlp, float* __restrict__ Olp,
    const float* __restrict__ Qrp, const float* __restrict__ Krp,
    const float* __restrict__ Vrp, float* __restrict__ Orp)
{
    extern __shared__ __align__(16) unsigned smw[];
    unsigned* Qh = smw;            // 4096
    unsigned* Qlo = smw + 4096;    // 4096
    unsigned* Kh = smw + 8192;     // 2048
    unsigned* Klo = smw + 10240;   // 2048
    unsigned* Vh = smw + 12288;    // 2048
    unsigned* Vlo = smw + 14336;   // 2048

    const int tid = threadIdx.x;
    const int lane = tid & 31, w = tid >> 5;
    const int path = blockIdx.z >> 1;
    const int bz = blockIdx.z & 1;
    const float* Q = path ? Qrp : Qlp;
    const float* Kg = path ? Krp : Klp;
    const float* V = path ? Vrp : Vlp;
    float* O = path ? Orp : Olp;

    const int qt = (gridDim.x - 1) - blockIdx.x;
    const int q0 = qt << 7;
    const size_t base = ((size_t)bz * EE + (size_t)blockIdx.y * DD) * SS;
    const float* Qp = Q + base;
    const float* Kp = Kg + base;
    const float* Vp = V + base;

#pragma unroll
    for (int i = 0; i < 4; ++i) {
        int s = tid + (i << 8);
        int ls = s & 31, kc = (s >> 5) & 3, wq = s >> 7;
        int qr_ = q0 + (wq << 4) + (ls >> 2);
        int d0 = (kc << 4) + ((ls & 3) << 1);
        const float* p00 = Qp + (size_t)d0 * SS + qr_;
        float f0a = p00[0],              f0b = p00[SS];
        float f1a = p00[8],              f1b = p00[SS + 8];
        float f2a = p00[(size_t)8 * SS], f2b = p00[(size_t)9 * SS];
        float f3a = p00[(size_t)8 * SS + 8], f3b = p00[(size_t)9 * SS + 8];
        unsigned h0 = bf2pack(f0a, f0b), h1 = bf2pack(f1a, f1b);
        unsigned h2 = bf2pack(f2a, f2b), h3 = bf2pack(f3a, f3b);
        unsigned l0 = bf2pack(f0a - bfhi(f0a), f0b - bfhi(f0b));
        unsigned l1 = bf2pack(f1a - bfhi(f1a), f1b - bfhi(f1b));
        unsigned l2 = bf2pack(f2a - bfhi(f2a), f2b - bfhi(f2b));
        unsigned l3 = bf2pack(f3a - bfhi(f3a), f3b - bfhi(f3b));
        *(uint4*)&Qh[s * 4]  = make_uint4(h0, h1, h2, h3);
        *(uint4*)&Qlo[s * 4] = make_uint4(l0, l1, l2, l3);
    }

    float o[8][4];
#pragma unroll
    for (int i = 0; i < 8; ++i)
#pragma unroll
        for (int j = 0; j < 4; ++j) o[i][j] = 0.f;
    float m0 = -1e30f, m1 = -1e30f, l0s = 0.f, l1s = 0.f;

    const int qg = q0 + (w << 4) + (lane >> 2);
    const int ntile = qt * 2 + 2;

    for (int kt = 0; kt < ntile; ++kt) {
        const int t0 = kt << 6;
        __syncthreads();
#pragma unroll
        for (int i = 0; i < 4; ++i) {
            int s = tid + (i << 8);
            int ls = s & 31, kc = (s >> 5) & 3, nt = s >> 7;
            int tt = t0 + (nt << 3) + (ls >> 2);
            int d0 = (kc << 4) + ((ls & 3) << 1);
            const float* p00 = Kp + (size_t)d0 * SS + tt;
            float f0a = p00[0], f0b = p00[SS];
            float f1a = p00[(size_t)8 * SS], f1b = p00[(size_t)9 * SS];
            *(uint2*)&Kh[s * 2] = make_uint2(bf2pack(f0a, f0b), bf2pack(f1a, f1b));
            *(uint2*)&Klo[s * 2] = make_uint2(
                bf2pack(f0a - bfhi(f0a), f0b - bfhi(f0b)),
                bf2pack(f1a - bfhi(f1a), f1b - bfhi(f1b)));
        }
#pragma unroll
        for (int i = 0; i < 4; ++i) {
            int s = tid + (i << 8);
            int ls = s & 31, tc = (s >> 5) & 3, ndt = s >> 7;
            int d = (ndt << 3) + (ls >> 2);
            int tt = t0 + (tc << 4) + ((ls & 3) << 1);
            const float* p00 = Vp + (size_t)d * SS + tt;
            float2 v0 = *(const float2*)p00;
            float2 v1 = *(const float2*)(p00 + 8);
            *(uint2*)&Vh[s * 2] = make_uint2(bf2pack(v0.x, v0.y), bf2pack(v1.x, v1.y));
            *(uint2*)&Vlo[s * 2] = make_uint2(
                bf2pack(v0.x - bfhi(v0.x), v0.y - bfhi(v0.y)),
                bf2pack(v1.x - bfhi(v1.x), v1.y - bfhi(v1.y)));
        }
        __syncthreads();

        float sreg[8][4];
#pragma unroll
        for (int i = 0; i < 8; ++i)
#pragma unroll
            for (int j = 0; j < 4; ++j) sreg[i][j] = 0.f;
#pragma unroll
        for (int kc = 0; kc < 4; ++kc) {
            int ai = ((w * 4 + kc) * 32 + lane);
            uint4 ah = *(const uint4*)&Qh[ai * 4];
            uint4 al = *(const uint4*)&Qlo[ai * 4];
#pragma unroll
            for (int nt = 0; nt < 8; ++nt) {
                int bi = ((nt * 4 + kc) * 32 + lane);
                uint2 bh = *(const uint2*)&Kh[bi * 2];
                uint2 bl = *(const uint2*)&Klo[bi * 2];
                float* c = sreg[nt];
                mma_bf16(c[0], c[1], c[2], c[3], ah.x, ah.y, ah.z, ah.w, bh.x, bh.y);
                mma_bf16(c[0], c[1], c[2], c[3], ah.x, ah.y, ah.z, ah.w, bl.x, bl.y);
                mma_bf16(c[0], c[1], c[2], c[3], al.x, al.y, al.z, al.w, bh.x, bh.y);
            }
        }

        float mx0 = m0, mx1 = m1;
#pragma unroll
        for (int nt = 0; nt < 8; ++nt) {
            int tb = t0 + (nt << 3) + ((lane & 3) << 1);
            if (tb > qg)     sreg[nt][0] = -1e30f;
            if (tb + 1 > qg) sreg[nt][1] = -1e30f;
            if (tb > qg + 8)     sreg[nt][2] = -1e30f;
            if (tb + 1 > qg + 8) sreg[nt][3] = -1e30f;
            mx0 = fmaxf(mx0, fmaxf(sreg[nt][0], sreg[nt][1]));
            mx1 = fmaxf(mx1, fmaxf(sreg[nt][2], sreg[nt][3]));
        }
        mx0 = fmaxf(mx0, __shfl_xor_sync(0xffffffffu, mx0, 1));
        mx0 = fmaxf(mx0, __shfl_xor_sync(0xffffffffu, mx0, 2));
        mx1 = fmaxf(mx1, __shfl_xor_sync(0xffffffffu, mx1, 1));
        mx1 = fmaxf(mx1, __shfl_xor_sync(0xffffffffu, mx1, 2));
        float corr0 = exp2p(m0 - mx0), corr1 = exp2p(m1 - mx1);
        m0 = mx0; m1 = mx1;
        l0s *= corr0; l1s *= corr1;
#pragma unroll
        for (int nt = 0; nt < 8; ++nt) {
            o[nt][0] *= corr0; o[nt][1] *= corr0;
            o[nt][2] *= corr1; o[nt][3] *= corr1;
        }
        float ls0 = 0.f, ls1 = 0.f;
#pragma unroll
        for (int nt = 0; nt < 8; ++nt) {
            float p0 = exp2p(sreg[nt][0] - mx0);
            float p1 = exp2p(sreg[nt][1] - mx0);
            float p2 = exp2p(sreg[nt][2] - mx1);
            float p3 = exp2p(sreg[nt][3] - mx1);
            sreg[nt][0] = p0; sreg[nt][1] = p1;
            sreg[nt][2] = p2; sreg[nt][3] = p3;
            ls0 += p0 + p1; ls1 += p2 + p3;
        }
        ls0 += __shfl_xor_sync(0xffffffffu, ls0, 1);
        ls0 += __shfl_xor_sync(0xffffffffu, ls0, 2);
        ls1 += __shfl_xor_sync(0xffffffffu, ls1, 1);
        ls1 += __shfl_xor_sync(0xffffffffu, ls1, 2);
        l0s += ls0; l1s += ls1;

#pragma unroll
        for (int j = 0; j < 4; ++j) {
            float* pA = sreg[2 * j];
            float* pB = sreg[2 * j + 1];
            unsigned ah0 = bf2pack(pA[0], pA[1]);
            unsigned ah1 = bf2pack(pA[2], pA[3]);
            unsigned ah2 = bf2pack(pB[0], pB[1]);
            unsigned ah3 = bf2pack(pB[2], pB[3]);
            unsigned al0 = bf2pack(pA[0] - bfhi(pA[0]), pA[1] - bfhi(pA[1]));
            unsigned al1 = bf2pack(pA[2] - bfhi(pA[2]), pA[3] - bfhi(pA[3]));
            unsigned al2 = bf2pack(pB[0] - bfhi(pB[0]), pB[1] - bfhi(pB[1]));
            unsigned al3 = bf2pack(pB[2] - bfhi(pB[2]), pB[3] - bfhi(pB[3]));
#pragma unroll
            for (int nt = 0; nt < 8; ++nt) {
                int bi = ((nt * 4 + j) * 32 + lane);
                uint2 bh = *(const uint2*)&Vh[bi * 2];
                uint2 bl = *(const uint2*)&Vlo[bi * 2];
                float* c = o[nt];
                mma_bf16(c[0], c[1], c[2], c[3], ah0, ah1, ah2, ah3, bh.x, bh.y);
                mma_bf16(c[0], c[1], c[2], c[3], ah0, ah1, ah2, ah3, bl.x, bl.y);
                mma_bf16(c[0], c[1], c[2], c[3], al0, al1, al2, al3, bh.x, bh.y);
            }
        }
    }

    const float inv0 = 1.f / l0s, inv1 = 1.f / l1s;
    float* Op = O + base;
#pragma unroll
    for (int nt = 0; nt < 8; ++nt) {
        int d = (nt << 3) + ((lane & 3) << 1);
        Op[(size_t)d * SS + qg]       = o[nt][0] * inv0;
        Op[(size_t)(d + 1) * SS + qg] = o[nt][1] * inv0;
        Op[(size_t)d * SS + qg + 8]       = o[nt][2] * inv1;
        Op[(size_t)(d + 1) * SS + qg + 8] = o[nt][3] * inv1;
    }
}

// ---------------------------------------------------------------------------
// lambda = exp(sum lam_q_l*lam_k_l) - exp(sum lam_q_r*lam_k_r) + 0.1
// ---------------------------------------------------------------------------
__global__ void lam_kernel(const float* __restrict__ ql, const float* __restrict__ kl,
                           const float* __restrict__ qr, const float* __restrict__ kr)
{
    const int t = threadIdx.x;
    float a = ql[t] * kl[t] + ql[t + 32] * kl[t + 32];
    float b = qr[t] * kr[t] + qr[t + 32] * kr[t + 32];
#pragma unroll
    for (int off = 16; off > 0; off >>= 1) {
        a += __shfl_xor_sync(0xffffffffu, a, off);
        b += __shfl_xor_sync(0xffffffffu, b, off);
    }
    if (t == 0) g_lam = expf(a) - expf(b) + 0.1f;
}

// ---------------------------------------------------------------------------
// combined = attn_l - lam*attn_r; LayerNorm over E (biased var, eps 1e-5).
// ---------------------------------------------------------------------------
__global__ __launch_bounds__(512) void ln_kernel(
    const float* __restrict__ al, const float* __restrict__ ar,
    const float* __restrict__ gg, const float* __restrict__ bbv,
    float* __restrict__ out)
{
    __shared__ float ps[16][32], pq[16][32], smu[32], srs[32];
    const int tid = threadIdx.x;
    const int ty = tid >> 5, sl = tid & 31;
    const int b = blockIdx.x >> 6;
    const int s = ((blockIdx.x & 63) << 5) + sl;
    const float lam = g_lam;
    const size_t col = (size_t)b * EE * SS + s;
    const int e0 = ty << 6;

    float sum = 0.f, sq = 0.f;
    for (int e = e0; e < e0 + 64; ++e) {
        size_t idx = col + (size_t)e * SS;
        float c = al[idx] - lam * ar[idx];
        sum += c; sq += c * c;
    }
    ps[ty][sl] = sum; pq[ty][sl] = sq;
    __syncthreads();
    if (ty == 0) {
        float ts = 0.f, tq = 0.f;
#pragma unroll
        for (int r = 0; r < 16; ++r) { ts += ps[r][sl]; tq += pq[r][sl]; }
        float mu = ts * (1.f / EE);
        float var = tq * (1.f / EE) - mu * mu;
        smu[sl] = mu;
        srs[sl] = rsqrtf(var + 1e-5f);
    }
    __syncthreads();
    const float mu = smu[sl], rs = srs[sl];
    for (int e = e0; e < e0 + 64; ++e) {
        size_t idx = col + (size_t)e * SS;
        float c = al[idx] - lam * ar[idx];
        out[idx] = (c - mu) * rs * gg[e] + bbv[e];
    }
}

// ---------------------------------------------------------------------------
// Launch
// ---------------------------------------------------------------------------
static float* sym_addr(const void* symbol)
{
    void* p = nullptr;
    cudaGetSymbolAddress(&p, symbol);
    return (float*)p;
}

extern "C" void kernel_launch(void* const* d_in, const int* in_sizes, int n_in,
                              void* d_out, int out_size)
{
    const float* left  = (const float*)d_in[0];
    const float* right = (const float*)d_in[1];
    const float* Wq_l  = (const float*)d_in[2];
    const float* Wk_l  = (const float*)d_in[3];
    const float* Wv_l  = (const float*)d_in[4];
    const float* Wq_r  = (const float*)d_in[5];
    const float* Wk_r  = (const float*)d_in[6];
    const float* Wv_r  = (const float*)d_in[7];
    const float* Wo    = (const float*)d_in[8];
    const float* lql   = (const float*)d_in[9];
    const float* lkl   = (const float*)d_in[10];
    const float* lqr   = (const float*)d_in[11];
    const float* lkr   = (const float*)d_in[12];
    const float* ln_g  = (const float*)d_in[13];
    const float* ln_b  = (const float*)d_in[14];
    const float* W1    = (const float*)d_in[15];
    const float* b1    = (const float*)d_in[16];
    const float* W2    = (const float*)d_in[17];
    const float* b2    = (const float*)d_in[18];
    float* out = (float*)d_out;

    float* ql = sym_addr(g_ql); float* kl = sym_addr(g_kl); float* vl = sym_addr(g_vl);
    float* qr = sym_addr(g_qr); float* kr = sym_addr(g_kr); float* vr = sym_addr(g_vr);
    float* al = sym_addr(g_al); float* ar = sym_addr(g_ar);
    float* lno = sym_addr(g_lnout);
    float* h1 = sym_addr(g_h1);
    float* wf = sym_addr(g_wf);

    // D^-0.5 * log2(e): scores come out in log2 domain (softmax-invariant)
    const float qscale = 0.125f * 1.4426950408889634f;

    cudaFuncSetAttribute(gemm_tc, cudaFuncAttributeMaxDynamicSharedMemorySize,
                         GEMM_SMEM);
    cudaFuncSetAttribute(gemm_qkv, cudaFuncAttributeMaxDynamicSharedMemorySize,
                         GEMM_SMEM);
    cudaFuncSetAttribute(attn_mma, cudaFuncAttributeMaxDynamicSharedMemorySize,
                         ATTN_SMEM);

    dim3 blk(256);
    dim3 gp(SS / 128, EE / 128, BB);         // (16, 8, 2)
    dim3 gp1(SS / 128, (2 * EE) / 128, BB);  // (16, 16, 2)
    dim3 gpw(EE / 128, (2 * EE) / 128, 1);   // Wf = W1 @ Wo precompute
    dim3 gq(SS / 128, EE / 128, 6 * BB);     // all 6 QKV GEMMs

    // Wf precompute early (independent of activations)
    gemm_tc<<<gpw, blk, GEMM_SMEM>>>(W1, Wo, wf, 2 * EE, EE, EE, nullptr, 1.f, 0);

    // QKV projections: one launch, 1536 blocks
    gemm_qkv<<<gq, blk, GEMM_SMEM>>>(Wq_l, Wk_l, Wv_l, Wq_r, Wk_r, Wv_r,
                                     left, right, ql, kl, vl, qr, kr, vr, qscale);

    // attention: both paths in one launch (z = path*2 + b)
    dim3 ga(SS / 128, HH, 2 * BB);           // (16, 16, 4)
    attn_mma<<<ga, 256, ATTN_SMEM>>>(ql, kl, vl, al, qr, kr, vr, ar);

    // lambda, combine + LN
    lam_kernel<<<1, 32>>>(lql, lkl, lqr, lkr);
    ln_kernel<<<BB * (SS / 32), 512>>>(al, ar, ln_g, ln_b, lno);

    // fused (W1@Wo) + relu, then W2 straight into d_out ([B,E,S])
    gemm_tc<<<gp1, blk, GEMM_SMEM>>>(wf, lno, h1,  2 * EE, EE,     SS, b1, 1.f, 1);
    gemm_tc<<<gp,  blk, GEMM_SMEM>>>(W2, h1,  out, EE,     2 * EE, SS, b2, 1.f, 0);
}